// round 13
// baseline (speedup 1.0000x reference)
#include <cuda_runtime.h>
#include <cuda_pipeline.h>
#include <math.h>
#include <cstdint>

// ---------------- problem constants ----------------
#define BATCH   4
#define SEQ     2048
#define DMODEL  768
#define NHEADS  12
#define DK      64
#define DFF     3072
#define MROWS   (BATCH*SEQ)          // 8192
#define EPS_LN  1e-6f
#define NEGINF  -1.0e9f

// ---------------- scratch (device globals; allocation-free) ----------------
__device__ float g_xn  [MROWS*DMODEL];
__device__ float g_qkv [3*MROWS*DMODEL];     // [q|k|v], each [B*H, S, 64]
__device__ float g_ctx [MROWS*DMODEL];
__device__ float g_x2  [MROWS*DMODEL];
__device__ float g_h   [MROWS*DFF];
__device__ float g_part[2*MROWS*DMODEL];     // split-K partials
// tf32-rounded weights (original [K,N] layout)
__device__ float g_wqkv[DMODEL*3*DMODEL];    // [768][2304] = [wq|wk|wv]
__device__ float g_w1r [DMODEL*DFF];
__device__ float g_w2r [DFF*DMODEL];
__device__ float g_wor [DMODEL*DMODEL];

// ---------------- helpers ----------------
__device__ __forceinline__ float tf32r(float x) {
    uint32_t y;
    asm("cvt.rna.tf32.f32 %0, %1;" : "=r"(y) : "f"(x));
    return __uint_as_float(y);
}

__device__ __forceinline__ uint32_t smem_u32(const void* p) {
    uint32_t a;
    asm("{ .reg .u64 t; cvta.to.shared.u64 t, %1; cvt.u32.u64 %0, t; }"
        : "=r"(a) : "l"(p));
    return a;
}

__device__ __forceinline__ void mma_tf32(float* d,
    uint32_t a0, uint32_t a1, uint32_t a2, uint32_t a3,
    uint32_t b0, uint32_t b1)
{
    asm volatile(
        "mma.sync.aligned.m16n8k8.row.col.f32.tf32.tf32.f32 "
        "{%0,%1,%2,%3}, {%4,%5,%6,%7}, {%8,%9}, {%0,%1,%2,%3};"
        : "+f"(d[0]), "+f"(d[1]), "+f"(d[2]), "+f"(d[3])
        : "r"(a0), "r"(a1), "r"(a2), "r"(a3), "r"(b0), "r"(b1));
}

__device__ __forceinline__ void ldsm_x4(uint32_t& r0, uint32_t& r1,
                                        uint32_t& r2, uint32_t& r3, uint32_t a)
{
    asm volatile("ldmatrix.sync.aligned.m8n8.x4.shared.b16 {%0,%1,%2,%3}, [%4];"
                 : "=r"(r0), "=r"(r1), "=r"(r2), "=r"(r3) : "r"(a));
}

// =====================================================================
// trunc kernels (weights stay [K,N])
// =====================================================================
__global__ void __launch_bounds__(256) trunc_kernel(
    const float* __restrict__ W, float* __restrict__ Wr, int n4)
{
    int i = blockIdx.x * 256 + threadIdx.x;
    if (i < n4) {
        float4 v = ((const float4*)W)[i];
        v.x = tf32r(v.x); v.y = tf32r(v.y);
        v.z = tf32r(v.z); v.w = tf32r(v.w);
        ((float4*)Wr)[i] = v;
    }
}

__global__ void __launch_bounds__(256) trunc_qkv_kernel(
    const float* __restrict__ wq, const float* __restrict__ wk,
    const float* __restrict__ wv, float* __restrict__ out)
{
    int i = blockIdx.x * 256 + threadIdx.x;
    if (i >= DMODEL * DMODEL / 4) return;
    int k = i / (DMODEL / 4);
    int c = (i % (DMODEL / 4)) * 4;
    const float* srcs[3] = {wq, wk, wv};
    #pragma unroll
    for (int t = 0; t < 3; t++) {
        float4 v = *(const float4*)&srcs[t][(size_t)k * DMODEL + c];
        v.x = tf32r(v.x); v.y = tf32r(v.y);
        v.z = tf32r(v.z); v.w = tf32r(v.w);
        *(float4*)&out[(size_t)k * (3 * DMODEL) + t * DMODEL + c] = v;
    }
}

// =====================================================================
// split-K reduce: out = p0 + p1 + bias + res     (N must divide by 4)
// =====================================================================
__global__ void __launch_bounds__(256) reduce2_kernel(
    const float* __restrict__ part, const float* __restrict__ bias,
    const float* __restrict__ res, float* __restrict__ out, int N)
{
    size_t i = (size_t)blockIdx.x * 256 + threadIdx.x;     // float4 index
    float4 a = ((const float4*)part)[i];
    float4 b = ((const float4*)part)[(size_t)MROWS * DMODEL / 4 + i];
    int col = (int)((i * 4) % N);
    float4 bv = *(const float4*)&bias[col];
    float4 r = ((const float4*)res)[i];
    float4 o;
    o.x = a.x + b.x + bv.x + r.x;
    o.y = a.y + b.y + bv.y + r.y;
    o.z = a.z + b.z + bv.z + r.z;
    o.w = a.w + b.w + bv.w + r.w;
    ((float4*)out)[i] = o;
}

// =====================================================================
// LayerNorm: warp-per-row, 8 rows/block (R8 WIN, unchanged)
// =====================================================================
__global__ void __launch_bounds__(256) ln_kernel(
    const float* __restrict__ x, float* __restrict__ o,
    const float* __restrict__ ga, const float* __restrict__ gb)
{
    int wid = threadIdx.x >> 5, lane = threadIdx.x & 31;
    size_t row = (size_t)blockIdx.x * 8 + wid;
    const float4* xr = (const float4*)(x + row * DMODEL);
    float4 v[6];
    float s = 0.f;
    #pragma unroll
    for (int j = 0; j < 6; j++) {
        v[j] = xr[lane + 32 * j];
        s += v[j].x + v[j].y + v[j].z + v[j].w;
    }
    #pragma unroll
    for (int off = 16; off; off >>= 1) s += __shfl_xor_sync(0xffffffffu, s, off);
    float mean = s * (1.0f / 768.0f);
    float ss = 0.f;
    #pragma unroll
    for (int j = 0; j < 6; j++) {
        v[j].x -= mean; v[j].y -= mean; v[j].z -= mean; v[j].w -= mean;
        ss += v[j].x * v[j].x + v[j].y * v[j].y + v[j].z * v[j].z + v[j].w * v[j].w;
    }
    #pragma unroll
    for (int off = 16; off; off >>= 1) ss += __shfl_xor_sync(0xffffffffu, ss, off);
    float stdv = sqrtf(ss * (1.0f / 767.0f));
    float sc = ga[0] / (EPS_LN + stdv);
    float bb = gb[0];
    float4* orow = (float4*)(o + row * DMODEL);
    #pragma unroll
    for (int j = 0; j < 6; j++) {
        float4 w;
        w.x = tf32r(v[j].x * sc + bb);
        w.y = tf32r(v[j].y * sc + bb);
        w.z = tf32r(v[j].z * sc + bb);
        w.w = tf32r(v[j].w * sc + bb);
        orow[lane + 32 * j] = w;
    }
}

// =====================================================================
// tf32 mma.sync GEMM (R11 mainloop) + split-K via gridDim.z.
// K = per-split length; lda = full A row stride. z picks K-slice;
// EPI_PART writes raw partials to C + z*M*N.
// =====================================================================
#define EPI_BIAS 0
#define EPI_RELU 1
#define EPI_RES  2
#define EPI_QKV3 3
#define EPI_PART 4

#define BM 128
#define BN 128
#define BKT 16
#define STG 4
#define APAD 20
#define BPAD 136
#define A_STG (BM*APAD)
#define B_STG (BKT*BPAD)
#define GEMM_SMEM ((STG*(A_STG+B_STG))*4)

__global__ void __launch_bounds__(128) mma_gemm_kernel(
    const float* __restrict__ A, const float* __restrict__ B,
    const float* __restrict__ bias, const float* __restrict__ bias2,
    const float* __restrict__ bias3, const float* __restrict__ res,
    float* __restrict__ C, int M, int N, int K, int lda, int epi)
{
    extern __shared__ float sm[];
    float* As = sm;
    float* Bs = sm + STG * A_STG;

    int tid = threadIdx.x;
    int wid = tid >> 5, lane = tid & 31;
    int g = lane >> 2, q = lane & 3;
    int wm = (wid >> 1) * 64;
    int wn = (wid & 1) * 64;
    int m0 = blockIdx.y * BM, n0 = blockIdx.x * BN;
    int kbase = blockIdx.z * K;                 // split-K offset

    const float* Ab = A + (size_t)m0 * lda + kbase;
    const float* Bb = B + (size_t)kbase * N + n0;
    if (epi == EPI_PART) C += (size_t)blockIdx.z * M * N;

    auto load_stage = [&](int st, int k0) {
        float* aS = As + st * A_STG;
        float* bS = Bs + st * B_STG;
        #pragma unroll
        for (int i = 0; i < 4; i++) {
            int c = tid + (i << 7);
            int m = c >> 2, k4 = (c & 3) << 2;
            __pipeline_memcpy_async(aS + m * APAD + k4,
                                    Ab + (size_t)m * lda + k0 + k4, 16);
        }
        #pragma unroll
        for (int i = 0; i < 4; i++) {
            int c = tid + (i << 7);
            int k = c >> 5, n4 = (c & 31) << 2;
            __pipeline_memcpy_async(bS + k * BPAD + n4,
                                    Bb + (size_t)(k0 + k) * N + n4, 16);
        }
    };

    uint32_t smb = smem_u32(sm);
    uint32_t aAddr[4];
    #pragma unroll
    for (int mt = 0; mt < 4; mt++)
        aAddr[mt] = smb + ((wm + mt * 16 + (lane & 15)) * APAD) * 4
                        + (lane >> 4) * 16;

    float acc[4][8][4];
    #pragma unroll
    for (int mt = 0; mt < 4; mt++)
        #pragma unroll
        for (int nt = 0; nt < 8; nt++)
            #pragma unroll
            for (int c = 0; c < 4; c++) acc[mt][nt][c] = 0.f;

    int nT = K >> 4;
    #pragma unroll
    for (int s = 0; s < STG - 1; s++) {
        load_stage(s, s << 4);
        __pipeline_commit();
    }

    for (int t = 0; t < nT; t++) {
        __pipeline_wait_prior(STG - 2);
        __syncthreads();
        int nx = t + STG - 1;
        if (nx < nT) load_stage(nx & (STG - 1), nx << 4);
        __pipeline_commit();

        int st = t & (STG - 1);
        uint32_t aOff = (uint32_t)(st * A_STG * 4);
        const float* bS = Bs + st * B_STG;

        #pragma unroll
        for (int kk = 0; kk < BKT; kk += 8) {
            uint32_t af[4][4], bf[8][2];
            #pragma unroll
            for (int mt = 0; mt < 4; mt++)
                ldsm_x4(af[mt][0], af[mt][1], af[mt][2], af[mt][3],
                        aAddr[mt] + aOff + kk * 4);
            #pragma unroll
            for (int nt = 0; nt < 8; nt++) {
                const float* bp = bS + (kk + q) * BPAD + wn + nt * 8 + g;
                bf[nt][0] = __float_as_uint(bp[0]);
                bf[nt][1] = __float_as_uint(bp[4 * BPAD]);
            }
            #pragma unroll
            for (int mt = 0; mt < 4; mt++)
                #pragma unroll
                for (int nt = 0; nt < 8; nt++)
                    mma_tf32(acc[mt][nt], af[mt][0], af[mt][1], af[mt][2], af[mt][3],
                             bf[nt][0], bf[nt][1]);
        }
    }

    // ----- epilogue -----
    #pragma unroll
    for (int mt = 0; mt < 4; mt++) {
        #pragma unroll
        for (int half = 0; half < 2; half++) {
            int row = m0 + wm + mt * 16 + g + half * 8;
            #pragma unroll
            for (int nt = 0; nt < 8; nt++) {
                int col = n0 + wn + nt * 8 + 2 * q;
                float c0 = acc[mt][nt][half * 2 + 0];
                float c1 = acc[mt][nt][half * 2 + 1];
                if (epi == EPI_PART) {
                    *(float2*)&C[(size_t)row * N + col] = make_float2(c0, c1);
                } else if (epi == EPI_QKV3) {
                    int t_ = col / DMODEL;            // 0=q 1=k 2=v
                    int within = col - t_ * DMODEL;
                    const float* bptr = (t_ == 0) ? bias : (t_ == 1) ? bias2 : bias3;
                    float2 bv = *(const float2*)&bptr[within];
                    c0 = tf32r(c0 + bv.x); c1 = tf32r(c1 + bv.y);
                    int b_ = row >> 11, s_ = row & 2047;
                    int h_ = within >> 6, d_ = within & 63;
                    size_t o = (size_t)t_ * (MROWS * DMODEL) +
                               (((size_t)(b_ * NHEADS + h_) * SEQ + s_) << 6) + d_;
                    *(float2*)&C[o] = make_float2(c0, c1);
                } else {
                    float2 bv = *(const float2*)&bias[col];
                    c0 += bv.x; c1 += bv.y;
                    if (epi == EPI_RELU) {
                        c0 = tf32r(fmaxf(c0, 0.f));
                        c1 = tf32r(fmaxf(c1, 0.f));
                    } else if (epi == EPI_RES) {
                        float2 r2 = *(const float2*)&res[(size_t)row * N + col];
                        c0 += r2.x; c1 += r2.y;
                    }
                    *(float2*)&C[(size_t)row * N + col] = make_float2(c0, c1);
                }
            }
        }
    }
}

// =====================================================================
// tf32 mma.sync flash attention (unchanged from R6/R7 WIN)
// =====================================================================
#define QS 68
#define KS 68
#define VS 72
#define PS 68
#define NKV 32
#define ATT_SQ   (128*QS)
#define ATT_SK   (64*KS)
#define ATT_SV   (64*VS)
#define ATT_SP   (128*PS)
#define ATTN_SMEM_BYTES ((ATT_SQ + 2*ATT_SK + 2*ATT_SV + ATT_SP)*4 + 2*64*4)

__global__ void __launch_bounds__(256) attn_mma_kernel(
    const float* __restrict__ Q, const float* __restrict__ K,
    const float* __restrict__ V, const int* __restrict__ mask,
    float* __restrict__ ctx)
{
    extern __shared__ float smf[];
    float* sQ = smf;
    float* sK = sQ + ATT_SQ;
    float* sV = sK + 2 * ATT_SK;
    float* sP = sV + 2 * ATT_SV;
    int*   sM = (int*)(sP + ATT_SP);

    int tid = threadIdx.x;
    int wid = tid >> 5, lane = tid & 31;
    int g = lane >> 2, q = lane & 3;
    int bh = blockIdx.y;
    int q0 = blockIdx.x * 128;
    int b  = bh / NHEADS;
    int h  = bh % NHEADS;

    const float* Qh = Q + (size_t)bh * SEQ * DK;
    const float* Kh = K + (size_t)bh * SEQ * DK;
    const float* Vh = V + (size_t)bh * SEQ * DK;
    const int* mrow = mask + b * SEQ;

    #pragma unroll
    for (int i = 0; i < 8; i++) {
        int c = tid + 256 * i;
        int r = c >> 4, c4 = (c & 15) << 2;
        *(float4*)&sQ[r * QS + c4] =
            *(const float4*)&Qh[(size_t)(q0 + r) * DK + c4];
    }

    auto loadKV = [&](int buf, int kv0) {
        #pragma unroll
        for (int i = 0; i < 4; i++) {
            int c = tid + 256 * i;
            int r = c >> 4, c4 = (c & 15) << 2;
            __pipeline_memcpy_async(&sK[buf * ATT_SK + r * KS + c4],
                                    &Kh[(size_t)(kv0 + r) * DK + c4], 16);
            __pipeline_memcpy_async(&sV[buf * ATT_SV + r * VS + c4],
                                    &Vh[(size_t)(kv0 + r) * DK + c4], 16);
        }
        if (tid < 64)
            __pipeline_memcpy_async(&sM[buf * 64 + tid], &mrow[kv0 + tid], 4);
    };

    loadKV(0, 0);
    __pipeline_commit();

    float m0 = -1e30f, m1 = -1e30f, l0 = 0.f, l1 = 0.f;
    float oacc[8][4];
    #pragma unroll
    for (int nt = 0; nt < 8; nt++)
        #pragma unroll
        for (int c = 0; c < 4; c++) oacc[nt][c] = 0.f;

    int wr0 = wid * 16;

    for (int t = 0; t < NKV; t++) {
        if (t + 1 < NKV) loadKV((t + 1) & 1, (t + 1) * 64);
        __pipeline_commit();
        __pipeline_wait_prior(1);
        __syncthreads();

        const float* bK = sK + (t & 1) * ATT_SK;
        const float* bV = sV + (t & 1) * ATT_SV;
        const int*   bM = sM + (t & 1) * 64;

        float sacc[8][4];
        #pragma unroll
        for (int nt = 0; nt < 8; nt++)
            #pragma unroll
            for (int c = 0; c < 4; c++) sacc[nt][c] = 0.f;

        #pragma unroll
        for (int kk = 0; kk < DK; kk += 8) {
            const float* ap = sQ + (wr0 + g) * QS + kk + q;
            uint32_t a0 = __float_as_uint(ap[0]);
            uint32_t a1 = __float_as_uint(ap[8 * QS]);
            uint32_t a2 = __float_as_uint(ap[4]);
            uint32_t a3 = __float_as_uint(ap[8 * QS + 4]);
            #pragma unroll
            for (int nt = 0; nt < 8; nt++) {
                const float* bp = bK + (nt * 8 + g) * KS + kk + q;
                mma_tf32(sacc[nt], a0, a1, a2, a3,
                         __float_as_uint(bp[0]), __float_as_uint(bp[4]));
            }
        }

        float mx0 = -1e30f, mx1 = -1e30f;
        #pragma unroll
        for (int nt = 0; nt < 8; nt++) {
            int c0i = nt * 8 + 2 * q;
            int mva = bM[c0i], mvb = bM[c0i + 1];
            sacc[nt][0] = mva ? sacc[nt][0] * 0.125f : NEGINF;
            sacc[nt][1] = mvb ? sacc[nt][1] * 0.125f : NEGINF;
            sacc[nt][2] = mva ? sacc[nt][2] * 0.125f : NEGINF;
            sacc[nt][3] = mvb ? sacc[nt][3] * 0.125f : NEGINF;
            mx0 = fmaxf(mx0, fmaxf(sacc[nt][0], sacc[nt][1]));
            mx1 = fmaxf(mx1, fmaxf(sacc[nt][2], sacc[nt][3]));
        }
        #pragma unroll
        for (int off = 1; off < 4; off <<= 1) {
            mx0 = fmaxf(mx0, __shfl_xor_sync(0xffffffffu, mx0, off));
            mx1 = fmaxf(mx1, __shfl_xor_sync(0xffffffffu, mx1, off));
        }
        float mn0 = fmaxf(m0, mx0), mn1 = fmaxf(m1, mx1);
        float cor0 = __expf(m0 - mn0), cor1 = __expf(m1 - mn1);
        float ls0 = 0.f, ls1 = 0.f;
        float* pr0 = sP + (wr0 + g) * PS;
        float* pr1 = pr0 + 8 * PS;
        #pragma unroll
        for (int nt = 0; nt < 8; nt++) {
            int c0i = nt * 8 + 2 * q;
            float p0 = __expf(sacc[nt][0] - mn0);
            float p1 = __expf(sacc[nt][1] - mn0);
            float p2 = __expf(sacc[nt][2] - mn1);
            float p3 = __expf(sacc[nt][3] - mn1);
            ls0 += p0 + p1; ls1 += p2 + p3;
            pr0[c0i]     = tf32r(p0);
            pr0[c0i + 1] = tf32r(p1);
            pr1[c0i]     = tf32r(p2);
            pr1[c0i + 1] = tf32r(p3);
        }
        #pragma unroll
        for (int off = 1; off < 4; off <<= 1) {
            ls0 += __shfl_xor_sync(0xffffffffu, ls0, off);
            ls1 += __shfl_xor_sync(0xffffffffu, ls1, off);
        }
        l0 = l0 * cor0 + ls0; m0 = mn0;
        l1 = l1 * cor1 + ls1; m1 = mn1;
        #pragma unroll
        for (int nt = 0; nt < 8; nt++) {
            oacc[nt][0] *= cor0; oacc[nt][1] *= cor0;
            oacc[nt][2] *= cor1; oacc[nt][3] *= cor1;
        }
        __syncwarp();

        #pragma unroll
        for (int kk = 0; kk < 64; kk += 8) {
            const float* ap = sP + (wr0 + g) * PS + kk + q;
            uint32_t a0 = __float_as_uint(ap[0]);
            uint32_t a1 = __float_as_uint(ap[8 * PS]);
            uint32_t a2 = __float_as_uint(ap[4]);
            uint32_t a3 = __float_as_uint(ap[8 * PS + 4]);
            #pragma unroll
            for (int nt = 0; nt < 8; nt++) {
                const float* bp = bV + (kk + q) * VS + nt * 8 + g;
                mma_tf32(oacc[nt], a0, a1, a2, a3,
                         __float_as_uint(bp[0]), __float_as_uint(bp[4 * VS]));
            }
        }
        __syncthreads();
    }

    float inv0 = 1.0f / l0, inv1 = 1.0f / l1;
    size_t row0 = (size_t)(b * SEQ + q0 + wr0 + g);
    size_t row1 = row0 + 8;
    #pragma unroll
    for (int nt = 0; nt < 8; nt++) {
        int col = h * DK + nt * 8 + 2 * q;
        *(float2*)&ctx[row0 * DMODEL + col] =
            make_float2(tf32r(oacc[nt][0] * inv0), tf32r(oacc[nt][1] * inv0));
        *(float2*)&ctx[row1 * DMODEL + col] =
            make_float2(tf32r(oacc[nt][2] * inv1), tf32r(oacc[nt][3] * inv1));
    }
}

// =====================================================================
// launcher
// =====================================================================
extern "C" void kernel_launch(void* const* d_in, const int* in_sizes, int n_in,
                              void* d_out, int out_size)
{
    const float* x    = (const float*)d_in[0];
    const int*   mask = (const int*)  d_in[1];
    const float* wq = (const float*)d_in[2],  *bq = (const float*)d_in[3];
    const float* wk = (const float*)d_in[4],  *bk = (const float*)d_in[5];
    const float* wv = (const float*)d_in[6],  *bv = (const float*)d_in[7];
    const float* wo = (const float*)d_in[8],  *bo = (const float*)d_in[9];
    const float* w1 = (const float*)d_in[10], *b1 = (const float*)d_in[11];
    const float* w2 = (const float*)d_in[12], *b2 = (const float*)d_in[13];
    const float* ln1a = (const float*)d_in[14], *ln1b = (const float*)d_in[15];
    const float* ln2a = (const float*)d_in[16], *ln2b = (const float*)d_in[17];
    float* out = (float*)d_out;

    float *xn, *qkv, *ctx, *x2, *hbuf, *part;
    float *wqkv, *wor, *w1r, *w2r;
    cudaGetSymbolAddress((void**)&xn,   g_xn);
    cudaGetSymbolAddress((void**)&qkv,  g_qkv);
    cudaGetSymbolAddress((void**)&ctx,  g_ctx);
    cudaGetSymbolAddress((void**)&x2,   g_x2);
    cudaGetSymbolAddress((void**)&hbuf, g_h);
    cudaGetSymbolAddress((void**)&part, g_part);
    cudaGetSymbolAddress((void**)&wqkv, g_wqkv);
    cudaGetSymbolAddress((void**)&wor,  g_wor);
    cudaGetSymbolAddress((void**)&w1r,  g_w1r);
    cudaGetSymbolAddress((void**)&w2r,  g_w2r);

    cudaFuncSetAttribute(attn_mma_kernel,
                         cudaFuncAttributeMaxDynamicSharedMemorySize,
                         ATTN_SMEM_BYTES);
    cudaFuncSetAttribute(mma_gemm_kernel,
                         cudaFuncAttributeMaxDynamicSharedMemorySize,
                         GEMM_SMEM);

    int n1 = DMODEL * DMODEL / 4, n2 = DMODEL * DFF / 4;
    trunc_qkv_kernel<<<(n1 + 255) / 256, 256>>>(wq, wk, wv, wqkv);
    trunc_kernel<<<(n1 + 255) / 256, 256>>>(wo, wor, n1);
    trunc_kernel<<<(n2 + 255) / 256, 256>>>(w1, w1r, n2);
    trunc_kernel<<<(n2 + 255) / 256, 256>>>(w2, w2r, n2);

    dim3 gQKV(3 * DMODEL / BN, MROWS / BM);      // (18, 64)
    dim3 gWO  (DMODEL / BN, MROWS / BM, 2);      // (6, 64, 2) split-K
    dim3 g3072(DFF    / BN, MROWS / BM);         // (24, 64)
    dim3 gW2  (DMODEL / BN, MROWS / BM, 2);      // (6, 64, 2) split-K
    int nRed = MROWS * DMODEL / 4 / 256;         // 6144 blocks

    float* qp = qkv;
    float* kp = qkv + (size_t)MROWS * DMODEL;
    float* vp = qkv + 2 * (size_t)MROWS * DMODEL;

    // sublayer 1
    ln_kernel<<<MROWS / 8, 256>>>(x, xn, ln1a, ln1b);
    mma_gemm_kernel<<<gQKV, 128, GEMM_SMEM>>>(xn, wqkv, bq, bk, bv, nullptr,
                                              qkv, MROWS, 3 * DMODEL, DMODEL, DMODEL, EPI_QKV3);
    attn_mma_kernel<<<dim3(SEQ / 128, BATCH * NHEADS), 256, ATTN_SMEM_BYTES>>>(qp, kp, vp, mask, ctx);
    // wo: split-K=2 (K 768 -> 2x384), partials then fused reduce (+bo +x)
    mma_gemm_kernel<<<gWO, 128, GEMM_SMEM>>>(ctx, wor, nullptr, nullptr, nullptr, nullptr,
                                             part, MROWS, DMODEL, DMODEL / 2, DMODEL, EPI_PART);
    reduce2_kernel<<<nRed, 256>>>(part, bo, x, x2, DMODEL);

    // sublayer 2
    ln_kernel<<<MROWS / 8, 256>>>(x2, xn, ln2a, ln2b);
    mma_gemm_kernel<<<g3072, 128, GEMM_SMEM>>>(xn, w1r, b1, nullptr, nullptr, nullptr,
                                               hbuf, MROWS, DFF, DMODEL, DMODEL, EPI_RELU);
    // w2: split-K=2 (K 3072 -> 2x1536), partials then fused reduce (+b2 +x2)
    mma_gemm_kernel<<<gW2, 128, GEMM_SMEM>>>(hbuf, w2r, nullptr, nullptr, nullptr, nullptr,
                                             part, MROWS, DMODEL, DFF / 2, DFF, EPI_PART);
    reduce2_kernel<<<nRed, 256>>>(part, b2, x2, out, DMODEL);
}

// round 14
// speedup vs baseline: 1.0421x; 1.0421x over previous
#include <cuda_runtime.h>
#include <cuda_pipeline.h>
#include <math.h>
#include <cstdint>

// ---------------- problem constants ----------------
#define BATCH   4
#define SEQ     2048
#define DMODEL  768
#define NHEADS  12
#define DK      64
#define DFF     3072
#define MROWS   (BATCH*SEQ)          // 8192
#define EPS_LN  1e-6f
#define NEGINF  -1.0e9f

// ---------------- scratch (device globals; allocation-free) ----------------
__device__ float g_xn  [MROWS*DMODEL];
__device__ float g_qkv [3*MROWS*DMODEL];     // [q|k|v], each [B*H, S, 64]
__device__ float g_ctx [MROWS*DMODEL];
__device__ float g_x2  [MROWS*DMODEL];
__device__ float g_h   [MROWS*DFF];
// tf32-rounded weights (original [K,N] layout)
__device__ float g_wqkv[DMODEL*3*DMODEL];    // [768][2304] = [wq|wk|wv]
__device__ float g_w1r [DMODEL*DFF];
__device__ float g_w2r [DFF*DMODEL];
__device__ float g_wor [DMODEL*DMODEL];

// ---------------- helpers ----------------
__device__ __forceinline__ float tf32r(float x) {
    uint32_t y;
    asm("cvt.rna.tf32.f32 %0, %1;" : "=r"(y) : "f"(x));
    return __uint_as_float(y);
}

__device__ __forceinline__ uint32_t smem_u32(const void* p) {
    uint32_t a;
    asm("{ .reg .u64 t; cvta.to.shared.u64 t, %1; cvt.u32.u64 %0, t; }"
        : "=r"(a) : "l"(p));
    return a;
}

__device__ __forceinline__ void mma_tf32(float* d,
    uint32_t a0, uint32_t a1, uint32_t a2, uint32_t a3,
    uint32_t b0, uint32_t b1)
{
    asm volatile(
        "mma.sync.aligned.m16n8k8.row.col.f32.tf32.tf32.f32 "
        "{%0,%1,%2,%3}, {%4,%5,%6,%7}, {%8,%9}, {%0,%1,%2,%3};"
        : "+f"(d[0]), "+f"(d[1]), "+f"(d[2]), "+f"(d[3])
        : "r"(a0), "r"(a1), "r"(a2), "r"(a3), "r"(b0), "r"(b1));
}

__device__ __forceinline__ void ldsm_x4(uint32_t& r0, uint32_t& r1,
                                        uint32_t& r2, uint32_t& r3, uint32_t a)
{
    asm volatile("ldmatrix.sync.aligned.m8n8.x4.shared.b16 {%0,%1,%2,%3}, [%4];"
                 : "=r"(r0), "=r"(r1), "=r"(r2), "=r"(r3) : "r"(a));
}

// =====================================================================
// trunc kernels (weights stay [K,N])
// =====================================================================
__global__ void __launch_bounds__(256) trunc_kernel(
    const float* __restrict__ W, float* __restrict__ Wr, int n4)
{
    int i = blockIdx.x * 256 + threadIdx.x;
    if (i < n4) {
        float4 v = ((const float4*)W)[i];
        v.x = tf32r(v.x); v.y = tf32r(v.y);
        v.z = tf32r(v.z); v.w = tf32r(v.w);
        ((float4*)Wr)[i] = v;
    }
}

__global__ void __launch_bounds__(256) trunc_qkv_kernel(
    const float* __restrict__ wq, const float* __restrict__ wk,
    const float* __restrict__ wv, float* __restrict__ out)
{
    int i = blockIdx.x * 256 + threadIdx.x;
    if (i >= DMODEL * DMODEL / 4) return;
    int k = i / (DMODEL / 4);
    int c = (i % (DMODEL / 4)) * 4;
    const float* srcs[3] = {wq, wk, wv};
    #pragma unroll
    for (int t = 0; t < 3; t++) {
        float4 v = *(const float4*)&srcs[t][(size_t)k * DMODEL + c];
        v.x = tf32r(v.x); v.y = tf32r(v.y);
        v.z = tf32r(v.z); v.w = tf32r(v.w);
        *(float4*)&out[(size_t)k * (3 * DMODEL) + t * DMODEL + c] = v;
    }
}

// =====================================================================
// LayerNorm: warp-per-row, 8 rows/block (R8 WIN, unchanged)
// =====================================================================
__global__ void __launch_bounds__(256) ln_kernel(
    const float* __restrict__ x, float* __restrict__ o,
    const float* __restrict__ ga, const float* __restrict__ gb)
{
    int wid = threadIdx.x >> 5, lane = threadIdx.x & 31;
    size_t row = (size_t)blockIdx.x * 8 + wid;
    const float4* xr = (const float4*)(x + row * DMODEL);
    float4 v[6];
    float s = 0.f;
    #pragma unroll
    for (int j = 0; j < 6; j++) {
        v[j] = xr[lane + 32 * j];
        s += v[j].x + v[j].y + v[j].z + v[j].w;
    }
    #pragma unroll
    for (int off = 16; off; off >>= 1) s += __shfl_xor_sync(0xffffffffu, s, off);
    float mean = s * (1.0f / 768.0f);
    float ss = 0.f;
    #pragma unroll
    for (int j = 0; j < 6; j++) {
        v[j].x -= mean; v[j].y -= mean; v[j].z -= mean; v[j].w -= mean;
        ss += v[j].x * v[j].x + v[j].y * v[j].y + v[j].z * v[j].z + v[j].w * v[j].w;
    }
    #pragma unroll
    for (int off = 16; off; off >>= 1) ss += __shfl_xor_sync(0xffffffffu, ss, off);
    float stdv = sqrtf(ss * (1.0f / 767.0f));
    float sc = ga[0] / (EPS_LN + stdv);
    float bb = gb[0];
    float4* orow = (float4*)(o + row * DMODEL);
    #pragma unroll
    for (int j = 0; j < 6; j++) {
        float4 w;
        w.x = tf32r(v[j].x * sc + bb);
        w.y = tf32r(v[j].y * sc + bb);
        w.z = tf32r(v[j].z * sc + bb);
        w.w = tf32r(v[j].w * sc + bb);
        orow[lane + 32 * j] = w;
    }
}

// =====================================================================
// tf32 mma.sync GEMM: 3-stage pipeline, __launch_bounds__(128,3) for
// 3 CTAs/SM (444 concurrent) — removes 2-wave tails on 384-CTA grids.
// C = epi(A[M,K] @ W[K,N] + bias). CTA 128x128, 4 warps (64x64 each).
// A smem [m][k] pad 20 (ldmatrix A frags); B smem [k][n] pad 136.
// =====================================================================
#define EPI_BIAS 0
#define EPI_RELU 1
#define EPI_RES  2
#define EPI_QKV3 3

#define BM 128
#define BN 128
#define BKT 16
#define STG 3
#define APAD 20
#define BPAD 136
#define A_STG (BM*APAD)
#define B_STG (BKT*BPAD)
#define GEMM_SMEM ((STG*(A_STG+B_STG))*4)      // 56832 B

__global__ void __launch_bounds__(128, 3) mma_gemm_kernel(
    const float* __restrict__ A, const float* __restrict__ B,
    const float* __restrict__ bias, const float* __restrict__ bias2,
    const float* __restrict__ bias3, const float* __restrict__ res,
    float* __restrict__ C, int M, int N, int K, int epi)
{
    extern __shared__ float sm[];
    float* As = sm;
    float* Bs = sm + STG * A_STG;

    int tid = threadIdx.x;
    int wid = tid >> 5, lane = tid & 31;
    int g = lane >> 2, q = lane & 3;
    int wm = (wid >> 1) * 64;
    int wn = (wid & 1) * 64;
    int m0 = blockIdx.y * BM, n0 = blockIdx.x * BN;

    const float* Ab = A + (size_t)m0 * K;
    const float* Bb = B + n0;

    auto load_stage = [&](int st, int k0) {
        float* aS = As + st * A_STG;
        float* bS = Bs + st * B_STG;
        #pragma unroll
        for (int i = 0; i < 4; i++) {
            int c = tid + (i << 7);
            int m = c >> 2, k4 = (c & 3) << 2;
            __pipeline_memcpy_async(aS + m * APAD + k4,
                                    Ab + (size_t)m * K + k0 + k4, 16);
        }
        #pragma unroll
        for (int i = 0; i < 4; i++) {
            int c = tid + (i << 7);
            int k = c >> 5, n4 = (c & 31) << 2;
            __pipeline_memcpy_async(bS + k * BPAD + n4,
                                    Bb + (size_t)(k0 + k) * N + n4, 16);
        }
    };

    uint32_t smb = smem_u32(sm);
    uint32_t aAddr[4];
    #pragma unroll
    for (int mt = 0; mt < 4; mt++)
        aAddr[mt] = smb + ((wm + mt * 16 + (lane & 15)) * APAD) * 4
                        + (lane >> 4) * 16;

    float acc[4][8][4];
    #pragma unroll
    for (int mt = 0; mt < 4; mt++)
        #pragma unroll
        for (int nt = 0; nt < 8; nt++)
            #pragma unroll
            for (int c = 0; c < 4; c++) acc[mt][nt][c] = 0.f;

    int nT = K >> 4;
    #pragma unroll
    for (int s = 0; s < STG - 1; s++) {
        load_stage(s, s << 4);
        __pipeline_commit();
    }

    int stCur = 0;
    for (int t = 0; t < nT; t++) {
        __pipeline_wait_prior(STG - 2);
        __syncthreads();
        int nx = t + STG - 1;
        int stNx = stCur + (STG - 1);
        if (stNx >= STG) stNx -= STG;
        if (nx < nT) load_stage(stNx, nx << 4);
        __pipeline_commit();

        uint32_t aOff = (uint32_t)(stCur * A_STG * 4);
        const float* bS = Bs + stCur * B_STG;

        #pragma unroll
        for (int kk = 0; kk < BKT; kk += 8) {
            uint32_t af[4][4], bf[8][2];
            #pragma unroll
            for (int mt = 0; mt < 4; mt++)
                ldsm_x4(af[mt][0], af[mt][1], af[mt][2], af[mt][3],
                        aAddr[mt] + aOff + kk * 4);
            #pragma unroll
            for (int nt = 0; nt < 8; nt++) {
                const float* bp = bS + (kk + q) * BPAD + wn + nt * 8 + g;
                bf[nt][0] = __float_as_uint(bp[0]);
                bf[nt][1] = __float_as_uint(bp[4 * BPAD]);
            }
            #pragma unroll
            for (int mt = 0; mt < 4; mt++)
                #pragma unroll
                for (int nt = 0; nt < 8; nt++)
                    mma_tf32(acc[mt][nt], af[mt][0], af[mt][1], af[mt][2], af[mt][3],
                             bf[nt][0], bf[nt][1]);
        }
        if (++stCur == STG) stCur = 0;
    }

    // ----- epilogue -----
    #pragma unroll
    for (int mt = 0; mt < 4; mt++) {
        #pragma unroll
        for (int half = 0; half < 2; half++) {
            int row = m0 + wm + mt * 16 + g + half * 8;
            #pragma unroll
            for (int nt = 0; nt < 8; nt++) {
                int col = n0 + wn + nt * 8 + 2 * q;
                float c0 = acc[mt][nt][half * 2 + 0];
                float c1 = acc[mt][nt][half * 2 + 1];
                if (epi == EPI_QKV3) {
                    int t_ = col / DMODEL;            // 0=q 1=k 2=v
                    int within = col - t_ * DMODEL;
                    const float* bptr = (t_ == 0) ? bias : (t_ == 1) ? bias2 : bias3;
                    float2 bv = *(const float2*)&bptr[within];
                    c0 = tf32r(c0 + bv.x); c1 = tf32r(c1 + bv.y);
                    int b_ = row >> 11, s_ = row & 2047;
                    int h_ = within >> 6, d_ = within & 63;
                    size_t o = (size_t)t_ * (MROWS * DMODEL) +
                               (((size_t)(b_ * NHEADS + h_) * SEQ + s_) << 6) + d_;
                    *(float2*)&C[o] = make_float2(c0, c1);
                } else {
                    float2 bv = *(const float2*)&bias[col];
                    c0 += bv.x; c1 += bv.y;
                    if (epi == EPI_RELU) {
                        c0 = tf32r(fmaxf(c0, 0.f));
                        c1 = tf32r(fmaxf(c1, 0.f));
                    } else if (epi == EPI_RES) {
                        float2 r2 = *(const float2*)&res[(size_t)row * N + col];
                        c0 += r2.x; c1 += r2.y;
                    }
                    *(float2*)&C[(size_t)row * N + col] = make_float2(c0, c1);
                }
            }
        }
    }
}

// =====================================================================
// tf32 mma.sync flash attention (unchanged from R6/R7 WIN)
// =====================================================================
#define QS 68
#define KS 68
#define VS 72
#define PS 68
#define NKV 32
#define ATT_SQ   (128*QS)
#define ATT_SK   (64*KS)
#define ATT_SV   (64*VS)
#define ATT_SP   (128*PS)
#define ATTN_SMEM_BYTES ((ATT_SQ + 2*ATT_SK + 2*ATT_SV + ATT_SP)*4 + 2*64*4)

__global__ void __launch_bounds__(256) attn_mma_kernel(
    const float* __restrict__ Q, const float* __restrict__ K,
    const float* __restrict__ V, const int* __restrict__ mask,
    float* __restrict__ ctx)
{
    extern __shared__ float smf[];
    float* sQ = smf;
    float* sK = sQ + ATT_SQ;
    float* sV = sK + 2 * ATT_SK;
    float* sP = sV + 2 * ATT_SV;
    int*   sM = (int*)(sP + ATT_SP);

    int tid = threadIdx.x;
    int wid = tid >> 5, lane = tid & 31;
    int g = lane >> 2, q = lane & 3;
    int bh = blockIdx.y;
    int q0 = blockIdx.x * 128;
    int b  = bh / NHEADS;
    int h  = bh % NHEADS;

    const float* Qh = Q + (size_t)bh * SEQ * DK;
    const float* Kh = K + (size_t)bh * SEQ * DK;
    const float* Vh = V + (size_t)bh * SEQ * DK;
    const int* mrow = mask + b * SEQ;

    #pragma unroll
    for (int i = 0; i < 8; i++) {
        int c = tid + 256 * i;
        int r = c >> 4, c4 = (c & 15) << 2;
        *(float4*)&sQ[r * QS + c4] =
            *(const float4*)&Qh[(size_t)(q0 + r) * DK + c4];
    }

    auto loadKV = [&](int buf, int kv0) {
        #pragma unroll
        for (int i = 0; i < 4; i++) {
            int c = tid + 256 * i;
            int r = c >> 4, c4 = (c & 15) << 2;
            __pipeline_memcpy_async(&sK[buf * ATT_SK + r * KS + c4],
                                    &Kh[(size_t)(kv0 + r) * DK + c4], 16);
            __pipeline_memcpy_async(&sV[buf * ATT_SV + r * VS + c4],
                                    &Vh[(size_t)(kv0 + r) * DK + c4], 16);
        }
        if (tid < 64)
            __pipeline_memcpy_async(&sM[buf * 64 + tid], &mrow[kv0 + tid], 4);
    };

    loadKV(0, 0);
    __pipeline_commit();

    float m0 = -1e30f, m1 = -1e30f, l0 = 0.f, l1 = 0.f;
    float oacc[8][4];
    #pragma unroll
    for (int nt = 0; nt < 8; nt++)
        #pragma unroll
        for (int c = 0; c < 4; c++) oacc[nt][c] = 0.f;

    int wr0 = wid * 16;

    for (int t = 0; t < NKV; t++) {
        if (t + 1 < NKV) loadKV((t + 1) & 1, (t + 1) * 64);
        __pipeline_commit();
        __pipeline_wait_prior(1);
        __syncthreads();

        const float* bK = sK + (t & 1) * ATT_SK;
        const float* bV = sV + (t & 1) * ATT_SV;
        const int*   bM = sM + (t & 1) * 64;

        float sacc[8][4];
        #pragma unroll
        for (int nt = 0; nt < 8; nt++)
            #pragma unroll
            for (int c = 0; c < 4; c++) sacc[nt][c] = 0.f;

        #pragma unroll
        for (int kk = 0; kk < DK; kk += 8) {
            const float* ap = sQ + (wr0 + g) * QS + kk + q;
            uint32_t a0 = __float_as_uint(ap[0]);
            uint32_t a1 = __float_as_uint(ap[8 * QS]);
            uint32_t a2 = __float_as_uint(ap[4]);
            uint32_t a3 = __float_as_uint(ap[8 * QS + 4]);
            #pragma unroll
            for (int nt = 0; nt < 8; nt++) {
                const float* bp = bK + (nt * 8 + g) * KS + kk + q;
                mma_tf32(sacc[nt], a0, a1, a2, a3,
                         __float_as_uint(bp[0]), __float_as_uint(bp[4]));
            }
        }

        float mx0 = -1e30f, mx1 = -1e30f;
        #pragma unroll
        for (int nt = 0; nt < 8; nt++) {
            int c0i = nt * 8 + 2 * q;
            int mva = bM[c0i], mvb = bM[c0i + 1];
            sacc[nt][0] = mva ? sacc[nt][0] * 0.125f : NEGINF;
            sacc[nt][1] = mvb ? sacc[nt][1] * 0.125f : NEGINF;
            sacc[nt][2] = mva ? sacc[nt][2] * 0.125f : NEGINF;
            sacc[nt][3] = mvb ? sacc[nt][3] * 0.125f : NEGINF;
            mx0 = fmaxf(mx0, fmaxf(sacc[nt][0], sacc[nt][1]));
            mx1 = fmaxf(mx1, fmaxf(sacc[nt][2], sacc[nt][3]));
        }
        #pragma unroll
        for (int off = 1; off < 4; off <<= 1) {
            mx0 = fmaxf(mx0, __shfl_xor_sync(0xffffffffu, mx0, off));
            mx1 = fmaxf(mx1, __shfl_xor_sync(0xffffffffu, mx1, off));
        }
        float mn0 = fmaxf(m0, mx0), mn1 = fmaxf(m1, mx1);
        float cor0 = __expf(m0 - mn0), cor1 = __expf(m1 - mn1);
        float ls0 = 0.f, ls1 = 0.f;
        float* pr0 = sP + (wr0 + g) * PS;
        float* pr1 = pr0 + 8 * PS;
        #pragma unroll
        for (int nt = 0; nt < 8; nt++) {
            int c0i = nt * 8 + 2 * q;
            float p0 = __expf(sacc[nt][0] - mn0);
            float p1 = __expf(sacc[nt][1] - mn0);
            float p2 = __expf(sacc[nt][2] - mn1);
            float p3 = __expf(sacc[nt][3] - mn1);
            ls0 += p0 + p1; ls1 += p2 + p3;
            pr0[c0i]     = tf32r(p0);
            pr0[c0i + 1] = tf32r(p1);
            pr1[c0i]     = tf32r(p2);
            pr1[c0i + 1] = tf32r(p3);
        }
        #pragma unroll
        for (int off = 1; off < 4; off <<= 1) {
            ls0 += __shfl_xor_sync(0xffffffffu, ls0, off);
            ls1 += __shfl_xor_sync(0xffffffffu, ls1, off);
        }
        l0 = l0 * cor0 + ls0; m0 = mn0;
        l1 = l1 * cor1 + ls1; m1 = mn1;
        #pragma unroll
        for (int nt = 0; nt < 8; nt++) {
            oacc[nt][0] *= cor0; oacc[nt][1] *= cor0;
            oacc[nt][2] *= cor1; oacc[nt][3] *= cor1;
        }
        __syncwarp();

        #pragma unroll
        for (int kk = 0; kk < 64; kk += 8) {
            const float* ap = sP + (wr0 + g) * PS + kk + q;
            uint32_t a0 = __float_as_uint(ap[0]);
            uint32_t a1 = __float_as_uint(ap[8 * PS]);
            uint32_t a2 = __float_as_uint(ap[4]);
            uint32_t a3 = __float_as_uint(ap[8 * PS + 4]);
            #pragma unroll
            for (int nt = 0; nt < 8; nt++) {
                const float* bp = bV + (kk + q) * VS + nt * 8 + g;
                mma_tf32(oacc[nt], a0, a1, a2, a3,
                         __float_as_uint(bp[0]), __float_as_uint(bp[4 * VS]));
            }
        }
        __syncthreads();
    }

    float inv0 = 1.0f / l0, inv1 = 1.0f / l1;
    size_t row0 = (size_t)(b * SEQ + q0 + wr0 + g);
    size_t row1 = row0 + 8;
    #pragma unroll
    for (int nt = 0; nt < 8; nt++) {
        int col = h * DK + nt * 8 + 2 * q;
        *(float2*)&ctx[row0 * DMODEL + col] =
            make_float2(tf32r(oacc[nt][0] * inv0), tf32r(oacc[nt][1] * inv0));
        *(float2*)&ctx[row1 * DMODEL + col] =
            make_float2(tf32r(oacc[nt][2] * inv1), tf32r(oacc[nt][3] * inv1));
    }
}

// =====================================================================
// launcher
// =====================================================================
extern "C" void kernel_launch(void* const* d_in, const int* in_sizes, int n_in,
                              void* d_out, int out_size)
{
    const float* x    = (const float*)d_in[0];
    const int*   mask = (const int*)  d_in[1];
    const float* wq = (const float*)d_in[2],  *bq = (const float*)d_in[3];
    const float* wk = (const float*)d_in[4],  *bk = (const float*)d_in[5];
    const float* wv = (const float*)d_in[6],  *bv = (const float*)d_in[7];
    const float* wo = (const float*)d_in[8],  *bo = (const float*)d_in[9];
    const float* w1 = (const float*)d_in[10], *b1 = (const float*)d_in[11];
    const float* w2 = (const float*)d_in[12], *b2 = (const float*)d_in[13];
    const float* ln1a = (const float*)d_in[14], *ln1b = (const float*)d_in[15];
    const float* ln2a = (const float*)d_in[16], *ln2b = (const float*)d_in[17];
    float* out = (float*)d_out;

    float *xn, *qkv, *ctx, *x2, *hbuf;
    float *wqkv, *wor, *w1r, *w2r;
    cudaGetSymbolAddress((void**)&xn,   g_xn);
    cudaGetSymbolAddress((void**)&qkv,  g_qkv);
    cudaGetSymbolAddress((void**)&ctx,  g_ctx);
    cudaGetSymbolAddress((void**)&x2,   g_x2);
    cudaGetSymbolAddress((void**)&hbuf, g_h);
    cudaGetSymbolAddress((void**)&wqkv, g_wqkv);
    cudaGetSymbolAddress((void**)&wor,  g_wor);
    cudaGetSymbolAddress((void**)&w1r,  g_w1r);
    cudaGetSymbolAddress((void**)&w2r,  g_w2r);

    cudaFuncSetAttribute(attn_mma_kernel,
                         cudaFuncAttributeMaxDynamicSharedMemorySize,
                         ATTN_SMEM_BYTES);
    cudaFuncSetAttribute(mma_gemm_kernel,
                         cudaFuncAttributeMaxDynamicSharedMemorySize,
                         GEMM_SMEM);

    int n1 = DMODEL * DMODEL / 4, n2 = DMODEL * DFF / 4;
    trunc_qkv_kernel<<<(n1 + 255) / 256, 256>>>(wq, wk, wv, wqkv);
    trunc_kernel<<<(n1 + 255) / 256, 256>>>(wo, wor, n1);
    trunc_kernel<<<(n2 + 255) / 256, 256>>>(w1, w1r, n2);
    trunc_kernel<<<(n2 + 255) / 256, 256>>>(w2, w2r, n2);

    dim3 gQKV(3 * DMODEL / BN, MROWS / BM);   // (18, 64)
    dim3 g768 (DMODEL / BN, MROWS / BM);      // (6, 64)
    dim3 g3072(DFF    / BN, MROWS / BM);      // (24, 64)

    float* qp = qkv;
    float* kp = qkv + (size_t)MROWS * DMODEL;
    float* vp = qkv + 2 * (size_t)MROWS * DMODEL;

    // sublayer 1
    ln_kernel<<<MROWS / 8, 256>>>(x, xn, ln1a, ln1b);
    mma_gemm_kernel<<<gQKV, 128, GEMM_SMEM>>>(xn, wqkv, bq, bk, bv, nullptr,
                                              qkv, MROWS, 3 * DMODEL, DMODEL, EPI_QKV3);
    attn_mma_kernel<<<dim3(SEQ / 128, BATCH * NHEADS), 256, ATTN_SMEM_BYTES>>>(qp, kp, vp, mask, ctx);
    mma_gemm_kernel<<<g768, 128, GEMM_SMEM>>>(ctx, wor, bo, nullptr, nullptr, x,
                                              x2, MROWS, DMODEL, DMODEL, EPI_RES);

    // sublayer 2
    ln_kernel<<<MROWS / 8, 256>>>(x2, xn, ln2a, ln2b);
    mma_gemm_kernel<<<g3072, 128, GEMM_SMEM>>>(xn, w1r, b1, nullptr, nullptr, nullptr,
                                               hbuf, MROWS, DFF, DMODEL, EPI_RELU);
    mma_gemm_kernel<<<g768, 128, GEMM_SMEM>>>(hbuf, w2r, b2, nullptr, nullptr, x2,
                                              out, MROWS, DMODEL, DFF, EPI_RES);
}

// round 15
// speedup vs baseline: 1.0917x; 1.0476x over previous
#include <cuda_runtime.h>
#include <cuda_pipeline.h>
#include <math.h>
#include <cstdint>

// ---------------- problem constants ----------------
#define BATCH   4
#define SEQ     2048
#define DMODEL  768
#define NHEADS  12
#define DK      64
#define DFF     3072
#define MROWS   (BATCH*SEQ)          // 8192
#define EPS_LN  1e-6f
#define NEGINF  -1.0e9f

// ---------------- scratch (device globals; allocation-free) ----------------
__device__ float g_xn  [MROWS*DMODEL];
__device__ float g_qkv [3*MROWS*DMODEL];     // [q|k|v], each [B*H, S, 64]
__device__ float g_ctx [MROWS*DMODEL];
__device__ float g_x2  [MROWS*DMODEL];
__device__ float g_h   [MROWS*DFF];
// tf32-rounded weights (original [K,N] layout)
__device__ float g_wqkv[DMODEL*3*DMODEL];    // [768][2304] = [wq|wk|wv]
__device__ float g_w1r [DMODEL*DFF];
__device__ float g_w2r [DFF*DMODEL];
__device__ float g_wor [DMODEL*DMODEL];

// ---------------- helpers ----------------
__device__ __forceinline__ float tf32r(float x) {
    uint32_t y;
    asm("cvt.rna.tf32.f32 %0, %1;" : "=r"(y) : "f"(x));
    return __uint_as_float(y);
}

__device__ __forceinline__ uint32_t smem_u32(const void* p) {
    uint32_t a;
    asm("{ .reg .u64 t; cvta.to.shared.u64 t, %1; cvt.u32.u64 %0, t; }"
        : "=r"(a) : "l"(p));
    return a;
}

__device__ __forceinline__ void mma_tf32(float* d,
    uint32_t a0, uint32_t a1, uint32_t a2, uint32_t a3,
    uint32_t b0, uint32_t b1)
{
    asm volatile(
        "mma.sync.aligned.m16n8k8.row.col.f32.tf32.tf32.f32 "
        "{%0,%1,%2,%3}, {%4,%5,%6,%7}, {%8,%9}, {%0,%1,%2,%3};"
        : "+f"(d[0]), "+f"(d[1]), "+f"(d[2]), "+f"(d[3])
        : "r"(a0), "r"(a1), "r"(a2), "r"(a3), "r"(b0), "r"(b1));
}

__device__ __forceinline__ void ldsm_x4(uint32_t& r0, uint32_t& r1,
                                        uint32_t& r2, uint32_t& r3, uint32_t a)
{
    asm volatile("ldmatrix.sync.aligned.m8n8.x4.shared.b16 {%0,%1,%2,%3}, [%4];"
                 : "=r"(r0), "=r"(r1), "=r"(r2), "=r"(r3) : "r"(a));
}

// =====================================================================
// trunc kernels (weights stay [K,N])
// =====================================================================
__global__ void __launch_bounds__(256) trunc_kernel(
    const float* __restrict__ W, float* __restrict__ Wr, int n4)
{
    int i = blockIdx.x * 256 + threadIdx.x;
    if (i < n4) {
        float4 v = ((const float4*)W)[i];
        v.x = tf32r(v.x); v.y = tf32r(v.y);
        v.z = tf32r(v.z); v.w = tf32r(v.w);
        ((float4*)Wr)[i] = v;
    }
}

__global__ void __launch_bounds__(256) trunc_qkv_kernel(
    const float* __restrict__ wq, const float* __restrict__ wk,
    const float* __restrict__ wv, float* __restrict__ out)
{
    int i = blockIdx.x * 256 + threadIdx.x;
    if (i >= DMODEL * DMODEL / 4) return;
    int k = i / (DMODEL / 4);
    int c = (i % (DMODEL / 4)) * 4;
    const float* srcs[3] = {wq, wk, wv};
    #pragma unroll
    for (int t = 0; t < 3; t++) {
        float4 v = *(const float4*)&srcs[t][(size_t)k * DMODEL + c];
        v.x = tf32r(v.x); v.y = tf32r(v.y);
        v.z = tf32r(v.z); v.w = tf32r(v.w);
        *(float4*)&out[(size_t)k * (3 * DMODEL) + t * DMODEL + c] = v;
    }
}

// =====================================================================
// LayerNorm: warp-per-row, 8 rows/block (R8 WIN, unchanged)
// =====================================================================
__global__ void __launch_bounds__(256) ln_kernel(
    const float* __restrict__ x, float* __restrict__ o,
    const float* __restrict__ ga, const float* __restrict__ gb)
{
    int wid = threadIdx.x >> 5, lane = threadIdx.x & 31;
    size_t row = (size_t)blockIdx.x * 8 + wid;
    const float4* xr = (const float4*)(x + row * DMODEL);
    float4 v[6];
    float s = 0.f;
    #pragma unroll
    for (int j = 0; j < 6; j++) {
        v[j] = xr[lane + 32 * j];
        s += v[j].x + v[j].y + v[j].z + v[j].w;
    }
    #pragma unroll
    for (int off = 16; off; off >>= 1) s += __shfl_xor_sync(0xffffffffu, s, off);
    float mean = s * (1.0f / 768.0f);
    float ss = 0.f;
    #pragma unroll
    for (int j = 0; j < 6; j++) {
        v[j].x -= mean; v[j].y -= mean; v[j].z -= mean; v[j].w -= mean;
        ss += v[j].x * v[j].x + v[j].y * v[j].y + v[j].z * v[j].z + v[j].w * v[j].w;
    }
    #pragma unroll
    for (int off = 16; off; off >>= 1) ss += __shfl_xor_sync(0xffffffffu, ss, off);
    float stdv = sqrtf(ss * (1.0f / 767.0f));
    float sc = ga[0] / (EPS_LN + stdv);
    float bb = gb[0];
    float4* orow = (float4*)(o + row * DMODEL);
    #pragma unroll
    for (int j = 0; j < 6; j++) {
        float4 w;
        w.x = tf32r(v[j].x * sc + bb);
        w.y = tf32r(v[j].y * sc + bb);
        w.z = tf32r(v[j].z * sc + bb);
        w.w = tf32r(v[j].w * sc + bb);
        orow[lane + 32 * j] = w;
    }
}

// =====================================================================
// tf32 mma.sync GEMM (R14 WIN: 3-stage, 3 CTAs/SM — unchanged)
// =====================================================================
#define EPI_BIAS 0
#define EPI_RELU 1
#define EPI_RES  2
#define EPI_QKV3 3

#define BM 128
#define BN 128
#define BKT 16
#define STG 3
#define APAD 20
#define BPAD 136
#define A_STG (BM*APAD)
#define B_STG (BKT*BPAD)
#define GEMM_SMEM ((STG*(A_STG+B_STG))*4)      // 56832 B

__global__ void __launch_bounds__(128, 3) mma_gemm_kernel(
    const float* __restrict__ A, const float* __restrict__ B,
    const float* __restrict__ bias, const float* __restrict__ bias2,
    const float* __restrict__ bias3, const float* __restrict__ res,
    float* __restrict__ C, int M, int N, int K, int epi)
{
    extern __shared__ float sm[];
    float* As = sm;
    float* Bs = sm + STG * A_STG;

    int tid = threadIdx.x;
    int wid = tid >> 5, lane = tid & 31;
    int g = lane >> 2, q = lane & 3;
    int wm = (wid >> 1) * 64;
    int wn = (wid & 1) * 64;
    int m0 = blockIdx.y * BM, n0 = blockIdx.x * BN;

    const float* Ab = A + (size_t)m0 * K;
    const float* Bb = B + n0;

    auto load_stage = [&](int st, int k0) {
        float* aS = As + st * A_STG;
        float* bS = Bs + st * B_STG;
        #pragma unroll
        for (int i = 0; i < 4; i++) {
            int c = tid + (i << 7);
            int m = c >> 2, k4 = (c & 3) << 2;
            __pipeline_memcpy_async(aS + m * APAD + k4,
                                    Ab + (size_t)m * K + k0 + k4, 16);
        }
        #pragma unroll
        for (int i = 0; i < 4; i++) {
            int c = tid + (i << 7);
            int k = c >> 5, n4 = (c & 31) << 2;
            __pipeline_memcpy_async(bS + k * BPAD + n4,
                                    Bb + (size_t)(k0 + k) * N + n4, 16);
        }
    };

    uint32_t smb = smem_u32(sm);
    uint32_t aAddr[4];
    #pragma unroll
    for (int mt = 0; mt < 4; mt++)
        aAddr[mt] = smb + ((wm + mt * 16 + (lane & 15)) * APAD) * 4
                        + (lane >> 4) * 16;

    float acc[4][8][4];
    #pragma unroll
    for (int mt = 0; mt < 4; mt++)
        #pragma unroll
        for (int nt = 0; nt < 8; nt++)
            #pragma unroll
            for (int c = 0; c < 4; c++) acc[mt][nt][c] = 0.f;

    int nT = K >> 4;
    #pragma unroll
    for (int s = 0; s < STG - 1; s++) {
        load_stage(s, s << 4);
        __pipeline_commit();
    }

    int stCur = 0;
    for (int t = 0; t < nT; t++) {
        __pipeline_wait_prior(STG - 2);
        __syncthreads();
        int nx = t + STG - 1;
        int stNx = stCur + (STG - 1);
        if (stNx >= STG) stNx -= STG;
        if (nx < nT) load_stage(stNx, nx << 4);
        __pipeline_commit();

        uint32_t aOff = (uint32_t)(stCur * A_STG * 4);
        const float* bS = Bs + stCur * B_STG;

        #pragma unroll
        for (int kk = 0; kk < BKT; kk += 8) {
            uint32_t af[4][4], bf[8][2];
            #pragma unroll
            for (int mt = 0; mt < 4; mt++)
                ldsm_x4(af[mt][0], af[mt][1], af[mt][2], af[mt][3],
                        aAddr[mt] + aOff + kk * 4);
            #pragma unroll
            for (int nt = 0; nt < 8; nt++) {
                const float* bp = bS + (kk + q) * BPAD + wn + nt * 8 + g;
                bf[nt][0] = __float_as_uint(bp[0]);
                bf[nt][1] = __float_as_uint(bp[4 * BPAD]);
            }
            #pragma unroll
            for (int mt = 0; mt < 4; mt++)
                #pragma unroll
                for (int nt = 0; nt < 8; nt++)
                    mma_tf32(acc[mt][nt], af[mt][0], af[mt][1], af[mt][2], af[mt][3],
                             bf[nt][0], bf[nt][1]);
        }
        if (++stCur == STG) stCur = 0;
    }

    // ----- epilogue -----
    #pragma unroll
    for (int mt = 0; mt < 4; mt++) {
        #pragma unroll
        for (int half = 0; half < 2; half++) {
            int row = m0 + wm + mt * 16 + g + half * 8;
            #pragma unroll
            for (int nt = 0; nt < 8; nt++) {
                int col = n0 + wn + nt * 8 + 2 * q;
                float c0 = acc[mt][nt][half * 2 + 0];
                float c1 = acc[mt][nt][half * 2 + 1];
                if (epi == EPI_QKV3) {
                    int t_ = col / DMODEL;            // 0=q 1=k 2=v
                    int within = col - t_ * DMODEL;
                    const float* bptr = (t_ == 0) ? bias : (t_ == 1) ? bias2 : bias3;
                    float2 bv = *(const float2*)&bptr[within];
                    c0 = tf32r(c0 + bv.x); c1 = tf32r(c1 + bv.y);
                    int b_ = row >> 11, s_ = row & 2047;
                    int h_ = within >> 6, d_ = within & 63;
                    size_t o = (size_t)t_ * (MROWS * DMODEL) +
                               (((size_t)(b_ * NHEADS + h_) * SEQ + s_) << 6) + d_;
                    *(float2*)&C[o] = make_float2(c0, c1);
                } else {
                    float2 bv = *(const float2*)&bias[col];
                    c0 += bv.x; c1 += bv.y;
                    if (epi == EPI_RELU) {
                        c0 = tf32r(fmaxf(c0, 0.f));
                        c1 = tf32r(fmaxf(c1, 0.f));
                    } else if (epi == EPI_RES) {
                        float2 r2 = *(const float2*)&res[(size_t)row * N + col];
                        c0 += r2.x; c1 += r2.y;
                    }
                    *(float2*)&C[(size_t)row * N + col] = make_float2(c0, c1);
                }
            }
        }
    }
}

// =====================================================================
// tf32 mma.sync flash attention — single-buffered K/V, 2 CTAs/SM.
// smem: sQ[128][68] + sK[64][68] + sV[64][72] + sP[128][68] + mask
//     = 105.9 KB  -> 2 CTAs/SM (was 141.8 KB / 1 CTA).
// Intra-CTA load/compute overlap traded for inter-CTA overlap.
// =====================================================================
#define QS 68
#define KS 68
#define VS 72
#define PS 68
#define NKV 32
#define ATT_SQ   (128*QS)
#define ATT_SK   (64*KS)
#define ATT_SV   (64*VS)
#define ATT_SP   (128*PS)
#define ATTN_SMEM_BYTES ((ATT_SQ + ATT_SK + ATT_SV + ATT_SP)*4 + 64*4)

__global__ void __launch_bounds__(256, 2) attn_mma_kernel(
    const float* __restrict__ Q, const float* __restrict__ K,
    const float* __restrict__ V, const int* __restrict__ mask,
    float* __restrict__ ctx)
{
    extern __shared__ float smf[];
    float* sQ = smf;                     // [128][QS]
    float* sK = sQ + ATT_SQ;             // [64][KS]
    float* sV = sK + ATT_SK;             // [64][VS]
    float* sP = sV + ATT_SV;             // [128][PS]
    int*   sM = (int*)(sP + ATT_SP);     // [64]

    int tid = threadIdx.x;
    int wid = tid >> 5, lane = tid & 31;
    int g = lane >> 2, q = lane & 3;
    int bh = blockIdx.y;
    int q0 = blockIdx.x * 128;
    int b  = bh / NHEADS;
    int h  = bh % NHEADS;

    const float* Qh = Q + (size_t)bh * SEQ * DK;
    const float* Kh = K + (size_t)bh * SEQ * DK;
    const float* Vh = V + (size_t)bh * SEQ * DK;
    const int* mrow = mask + b * SEQ;

    #pragma unroll
    for (int i = 0; i < 8; i++) {
        int c = tid + 256 * i;
        int r = c >> 4, c4 = (c & 15) << 2;
        *(float4*)&sQ[r * QS + c4] =
            *(const float4*)&Qh[(size_t)(q0 + r) * DK + c4];
    }

    auto loadKV = [&](int kv0) {
        #pragma unroll
        for (int i = 0; i < 4; i++) {
            int c = tid + 256 * i;
            int r = c >> 4, c4 = (c & 15) << 2;
            __pipeline_memcpy_async(&sK[r * KS + c4],
                                    &Kh[(size_t)(kv0 + r) * DK + c4], 16);
            __pipeline_memcpy_async(&sV[r * VS + c4],
                                    &Vh[(size_t)(kv0 + r) * DK + c4], 16);
        }
        if (tid < 64)
            __pipeline_memcpy_async(&sM[tid], &mrow[kv0 + tid], 4);
    };

    float m0 = -1e30f, m1 = -1e30f, l0 = 0.f, l1 = 0.f;
    float oacc[8][4];
    #pragma unroll
    for (int nt = 0; nt < 8; nt++)
        #pragma unroll
        for (int c = 0; c < 4; c++) oacc[nt][c] = 0.f;

    int wr0 = wid * 16;
    __syncthreads();   // sQ visible

    for (int t = 0; t < NKV; t++) {
        // single-buffer: all warps done with previous sK/sV before overwrite
        loadKV(t * 64);
        __pipeline_commit();
        __pipeline_wait_prior(0);
        __syncthreads();

        // ---- S = Q @ K^T ----
        float sacc[8][4];
        #pragma unroll
        for (int nt = 0; nt < 8; nt++)
            #pragma unroll
            for (int c = 0; c < 4; c++) sacc[nt][c] = 0.f;

        #pragma unroll
        for (int kk = 0; kk < DK; kk += 8) {
            const float* ap = sQ + (wr0 + g) * QS + kk + q;
            uint32_t a0 = __float_as_uint(ap[0]);
            uint32_t a1 = __float_as_uint(ap[8 * QS]);
            uint32_t a2 = __float_as_uint(ap[4]);
            uint32_t a3 = __float_as_uint(ap[8 * QS + 4]);
            #pragma unroll
            for (int nt = 0; nt < 8; nt++) {
                const float* bp = sK + (nt * 8 + g) * KS + kk + q;
                mma_tf32(sacc[nt], a0, a1, a2, a3,
                         __float_as_uint(bp[0]), __float_as_uint(bp[4]));
            }
        }

        // ---- scale + mask + online softmax (warp-local) ----
        float mx0 = -1e30f, mx1 = -1e30f;
        #pragma unroll
        for (int nt = 0; nt < 8; nt++) {
            int c0i = nt * 8 + 2 * q;
            int mva = sM[c0i], mvb = sM[c0i + 1];
            sacc[nt][0] = mva ? sacc[nt][0] * 0.125f : NEGINF;
            sacc[nt][1] = mvb ? sacc[nt][1] * 0.125f : NEGINF;
            sacc[nt][2] = mva ? sacc[nt][2] * 0.125f : NEGINF;
            sacc[nt][3] = mvb ? sacc[nt][3] * 0.125f : NEGINF;
            mx0 = fmaxf(mx0, fmaxf(sacc[nt][0], sacc[nt][1]));
            mx1 = fmaxf(mx1, fmaxf(sacc[nt][2], sacc[nt][3]));
        }
        #pragma unroll
        for (int off = 1; off < 4; off <<= 1) {
            mx0 = fmaxf(mx0, __shfl_xor_sync(0xffffffffu, mx0, off));
            mx1 = fmaxf(mx1, __shfl_xor_sync(0xffffffffu, mx1, off));
        }
        float mn0 = fmaxf(m0, mx0), mn1 = fmaxf(m1, mx1);
        float cor0 = __expf(m0 - mn0), cor1 = __expf(m1 - mn1);
        float ls0 = 0.f, ls1 = 0.f;
        float* pr0 = sP + (wr0 + g) * PS;
        float* pr1 = pr0 + 8 * PS;
        #pragma unroll
        for (int nt = 0; nt < 8; nt++) {
            int c0i = nt * 8 + 2 * q;
            float p0 = __expf(sacc[nt][0] - mn0);
            float p1 = __expf(sacc[nt][1] - mn0);
            float p2 = __expf(sacc[nt][2] - mn1);
            float p3 = __expf(sacc[nt][3] - mn1);
            ls0 += p0 + p1; ls1 += p2 + p3;
            pr0[c0i]     = tf32r(p0);
            pr0[c0i + 1] = tf32r(p1);
            pr1[c0i]     = tf32r(p2);
            pr1[c0i + 1] = tf32r(p3);
        }
        #pragma unroll
        for (int off = 1; off < 4; off <<= 1) {
            ls0 += __shfl_xor_sync(0xffffffffu, ls0, off);
            ls1 += __shfl_xor_sync(0xffffffffu, ls1, off);
        }
        l0 = l0 * cor0 + ls0; m0 = mn0;
        l1 = l1 * cor1 + ls1; m1 = mn1;
        #pragma unroll
        for (int nt = 0; nt < 8; nt++) {
            oacc[nt][0] *= cor0; oacc[nt][1] *= cor0;
            oacc[nt][2] *= cor1; oacc[nt][3] *= cor1;
        }
        __syncwarp();

        // ---- O += P @ V ----
        #pragma unroll
        for (int kk = 0; kk < 64; kk += 8) {
            const float* ap = sP + (wr0 + g) * PS + kk + q;
            uint32_t a0 = __float_as_uint(ap[0]);
            uint32_t a1 = __float_as_uint(ap[8 * PS]);
            uint32_t a2 = __float_as_uint(ap[4]);
            uint32_t a3 = __float_as_uint(ap[8 * PS + 4]);
            #pragma unroll
            for (int nt = 0; nt < 8; nt++) {
                const float* bp = sV + (kk + q) * VS + nt * 8 + g;
                mma_tf32(oacc[nt], a0, a1, a2, a3,
                         __float_as_uint(bp[0]), __float_as_uint(bp[4 * VS]));
            }
        }
        __syncthreads();   // all warps done with sK/sV before next overwrite
    }

    float inv0 = 1.0f / l0, inv1 = 1.0f / l1;
    size_t row0 = (size_t)(b * SEQ + q0 + wr0 + g);
    size_t row1 = row0 + 8;
    #pragma unroll
    for (int nt = 0; nt < 8; nt++) {
        int col = h * DK + nt * 8 + 2 * q;
        *(float2*)&ctx[row0 * DMODEL + col] =
            make_float2(tf32r(oacc[nt][0] * inv0), tf32r(oacc[nt][1] * inv0));
        *(float2*)&ctx[row1 * DMODEL + col] =
            make_float2(tf32r(oacc[nt][2] * inv1), tf32r(oacc[nt][3] * inv1));
    }
}

// =====================================================================
// launcher
// =====================================================================
extern "C" void kernel_launch(void* const* d_in, const int* in_sizes, int n_in,
                              void* d_out, int out_size)
{
    const float* x    = (const float*)d_in[0];
    const int*   mask = (const int*)  d_in[1];
    const float* wq = (const float*)d_in[2],  *bq = (const float*)d_in[3];
    const float* wk = (const float*)d_in[4],  *bk = (const float*)d_in[5];
    const float* wv = (const float*)d_in[6],  *bv = (const float*)d_in[7];
    const float* wo = (const float*)d_in[8],  *bo = (const float*)d_in[9];
    const float* w1 = (const float*)d_in[10], *b1 = (const float*)d_in[11];
    const float* w2 = (const float*)d_in[12], *b2 = (const float*)d_in[13];
    const float* ln1a = (const float*)d_in[14], *ln1b = (const float*)d_in[15];
    const float* ln2a = (const float*)d_in[16], *ln2b = (const float*)d_in[17];
    float* out = (float*)d_out;

    float *xn, *qkv, *ctx, *x2, *hbuf;
    float *wqkv, *wor, *w1r, *w2r;
    cudaGetSymbolAddress((void**)&xn,   g_xn);
    cudaGetSymbolAddress((void**)&qkv,  g_qkv);
    cudaGetSymbolAddress((void**)&ctx,  g_ctx);
    cudaGetSymbolAddress((void**)&x2,   g_x2);
    cudaGetSymbolAddress((void**)&hbuf, g_h);
    cudaGetSymbolAddress((void**)&wqkv, g_wqkv);
    cudaGetSymbolAddress((void**)&wor,  g_wor);
    cudaGetSymbolAddress((void**)&w1r,  g_w1r);
    cudaGetSymbolAddress((void**)&w2r,  g_w2r);

    cudaFuncSetAttribute(attn_mma_kernel,
                         cudaFuncAttributeMaxDynamicSharedMemorySize,
                         ATTN_SMEM_BYTES);
    cudaFuncSetAttribute(mma_gemm_kernel,
                         cudaFuncAttributeMaxDynamicSharedMemorySize,
                         GEMM_SMEM);

    int n1 = DMODEL * DMODEL / 4, n2 = DMODEL * DFF / 4;
    trunc_qkv_kernel<<<(n1 + 255) / 256, 256>>>(wq, wk, wv, wqkv);
    trunc_kernel<<<(n1 + 255) / 256, 256>>>(wo, wor, n1);
    trunc_kernel<<<(n2 + 255) / 256, 256>>>(w1, w1r, n2);
    trunc_kernel<<<(n2 + 255) / 256, 256>>>(w2, w2r, n2);

    dim3 gQKV(3 * DMODEL / BN, MROWS / BM);   // (18, 64)
    dim3 g768 (DMODEL / BN, MROWS / BM);      // (6, 64)
    dim3 g3072(DFF    / BN, MROWS / BM);      // (24, 64)

    float* qp = qkv;
    float* kp = qkv + (size_t)MROWS * DMODEL;
    float* vp = qkv + 2 * (size_t)MROWS * DMODEL;

    // sublayer 1
    ln_kernel<<<MROWS / 8, 256>>>(x, xn, ln1a, ln1b);
    mma_gemm_kernel<<<gQKV, 128, GEMM_SMEM>>>(xn, wqkv, bq, bk, bv, nullptr,
                                              qkv, MROWS, 3 * DMODEL, DMODEL, EPI_QKV3);
    attn_mma_kernel<<<dim3(SEQ / 128, BATCH * NHEADS), 256, ATTN_SMEM_BYTES>>>(qp, kp, vp, mask, ctx);
    mma_gemm_kernel<<<g768, 128, GEMM_SMEM>>>(ctx, wor, bo, nullptr, nullptr, x,
                                              x2, MROWS, DMODEL, DMODEL, EPI_RES);

    // sublayer 2
    ln_kernel<<<MROWS / 8, 256>>>(x2, xn, ln2a, ln2b);
    mma_gemm_kernel<<<g3072, 128, GEMM_SMEM>>>(xn, w1r, b1, nullptr, nullptr, nullptr,
                                               hbuf, MROWS, DFF, DMODEL, EPI_RELU);
    mma_gemm_kernel<<<g768, 128, GEMM_SMEM>>>(hbuf, w2r, b2, nullptr, nullptr, x2,
                                              out, MROWS, DMODEL, DFF, EPI_RES);
}

// round 16
// speedup vs baseline: 1.0988x; 1.0065x over previous
#include <cuda_runtime.h>
#include <cuda_pipeline.h>
#include <math.h>
#include <cstdint>

// ---------------- problem constants ----------------
#define BATCH   4
#define SEQ     2048
#define DMODEL  768
#define NHEADS  12
#define DK      64
#define DFF     3072
#define MROWS   (BATCH*SEQ)          // 8192
#define EPS_LN  1e-6f
#define NEGINF  -1.0e9f

// ---------------- scratch (device globals; allocation-free) ----------------
__device__ float g_xn  [MROWS*DMODEL];
__device__ float g_qkv [3*MROWS*DMODEL];     // [q|k|v], each [B*H, S, 64]
__device__ float g_ctx [MROWS*DMODEL];
__device__ float g_x2  [MROWS*DMODEL];
__device__ float g_h   [MROWS*DFF];
// tf32-rounded concat QKV weights (layout [768][2304] = [wq|wk|wv])
__device__ float g_wqkv[DMODEL*3*DMODEL];

// ---------------- helpers ----------------
__device__ __forceinline__ float tf32r(float x) {
    uint32_t y;
    asm("cvt.rna.tf32.f32 %0, %1;" : "=r"(y) : "f"(x));
    return __uint_as_float(y);
}

__device__ __forceinline__ uint32_t smem_u32(const void* p) {
    uint32_t a;
    asm("{ .reg .u64 t; cvta.to.shared.u64 t, %1; cvt.u32.u64 %0, t; }"
        : "=r"(a) : "l"(p));
    return a;
}

__device__ __forceinline__ void mma_tf32(float* d,
    uint32_t a0, uint32_t a1, uint32_t a2, uint32_t a3,
    uint32_t b0, uint32_t b1)
{
    asm volatile(
        "mma.sync.aligned.m16n8k8.row.col.f32.tf32.tf32.f32 "
        "{%0,%1,%2,%3}, {%4,%5,%6,%7}, {%8,%9}, {%0,%1,%2,%3};"
        : "+f"(d[0]), "+f"(d[1]), "+f"(d[2]), "+f"(d[3])
        : "r"(a0), "r"(a1), "r"(a2), "r"(a3), "r"(b0), "r"(b1));
}

__device__ __forceinline__ void ldsm_x4(uint32_t& r0, uint32_t& r1,
                                        uint32_t& r2, uint32_t& r3, uint32_t a)
{
    asm volatile("ldmatrix.sync.aligned.m8n8.x4.shared.b16 {%0,%1,%2,%3}, [%4];"
                 : "=r"(r0), "=r"(r1), "=r"(r2), "=r"(r3) : "r"(a));
}

// =====================================================================
// QKV concat + tf32-round (needed for fused QKV layout; kept rounded)
// =====================================================================
__global__ void __launch_bounds__(256) trunc_qkv_kernel(
    const float* __restrict__ wq, const float* __restrict__ wk,
    const float* __restrict__ wv, float* __restrict__ out)
{
    int i = blockIdx.x * 256 + threadIdx.x;
    if (i >= DMODEL * DMODEL / 4) return;
    int k = i / (DMODEL / 4);
    int c = (i % (DMODEL / 4)) * 4;
    const float* srcs[3] = {wq, wk, wv};
    #pragma unroll
    for (int t = 0; t < 3; t++) {
        float4 v = *(const float4*)&srcs[t][(size_t)k * DMODEL + c];
        v.x = tf32r(v.x); v.y = tf32r(v.y);
        v.z = tf32r(v.z); v.w = tf32r(v.w);
        *(float4*)&out[(size_t)k * (3 * DMODEL) + t * DMODEL + c] = v;
    }
}

// =====================================================================
// LayerNorm: warp-per-row, 8 rows/block (R8 WIN, unchanged)
// =====================================================================
__global__ void __launch_bounds__(256) ln_kernel(
    const float* __restrict__ x, float* __restrict__ o,
    const float* __restrict__ ga, const float* __restrict__ gb)
{
    int wid = threadIdx.x >> 5, lane = threadIdx.x & 31;
    size_t row = (size_t)blockIdx.x * 8 + wid;
    const float4* xr = (const float4*)(x + row * DMODEL);
    float4 v[6];
    float s = 0.f;
    #pragma unroll
    for (int j = 0; j < 6; j++) {
        v[j] = xr[lane + 32 * j];
        s += v[j].x + v[j].y + v[j].z + v[j].w;
    }
    #pragma unroll
    for (int off = 16; off; off >>= 1) s += __shfl_xor_sync(0xffffffffu, s, off);
    float mean = s * (1.0f / 768.0f);
    float ss = 0.f;
    #pragma unroll
    for (int j = 0; j < 6; j++) {
        v[j].x -= mean; v[j].y -= mean; v[j].z -= mean; v[j].w -= mean;
        ss += v[j].x * v[j].x + v[j].y * v[j].y + v[j].z * v[j].z + v[j].w * v[j].w;
    }
    #pragma unroll
    for (int off = 16; off; off >>= 1) ss += __shfl_xor_sync(0xffffffffu, ss, off);
    float stdv = sqrtf(ss * (1.0f / 767.0f));
    float sc = ga[0] / (EPS_LN + stdv);
    float bb = gb[0];
    float4* orow = (float4*)(o + row * DMODEL);
    #pragma unroll
    for (int j = 0; j < 6; j++) {
        float4 w;
        w.x = tf32r(v[j].x * sc + bb);
        w.y = tf32r(v[j].y * sc + bb);
        w.z = tf32r(v[j].z * sc + bb);
        w.w = tf32r(v[j].w * sc + bb);
        orow[lane + 32 * j] = w;
    }
}

// =====================================================================
// tf32 mma.sync GEMM (R14 WIN: 3-stage, 3 CTAs/SM — unchanged).
// B may be raw fp32 (HW truncates to tf32 internally).
// =====================================================================
#define EPI_BIAS 0
#define EPI_RELU 1
#define EPI_RES  2
#define EPI_QKV3 3

#define BM 128
#define BN 128
#define BKT 16
#define STG 3
#define APAD 20
#define BPAD 136
#define A_STG (BM*APAD)
#define B_STG (BKT*BPAD)
#define GEMM_SMEM ((STG*(A_STG+B_STG))*4)      // 56832 B

__global__ void __launch_bounds__(128, 3) mma_gemm_kernel(
    const float* __restrict__ A, const float* __restrict__ B,
    const float* __restrict__ bias, const float* __restrict__ bias2,
    const float* __restrict__ bias3, const float* __restrict__ res,
    float* __restrict__ C, int M, int N, int K, int epi)
{
    extern __shared__ float sm[];
    float* As = sm;
    float* Bs = sm + STG * A_STG;

    int tid = threadIdx.x;
    int wid = tid >> 5, lane = tid & 31;
    int g = lane >> 2, q = lane & 3;
    int wm = (wid >> 1) * 64;
    int wn = (wid & 1) * 64;
    int m0 = blockIdx.y * BM, n0 = blockIdx.x * BN;

    const float* Ab = A + (size_t)m0 * K;
    const float* Bb = B + n0;

    auto load_stage = [&](int st, int k0) {
        float* aS = As + st * A_STG;
        float* bS = Bs + st * B_STG;
        #pragma unroll
        for (int i = 0; i < 4; i++) {
            int c = tid + (i << 7);
            int m = c >> 2, k4 = (c & 3) << 2;
            __pipeline_memcpy_async(aS + m * APAD + k4,
                                    Ab + (size_t)m * K + k0 + k4, 16);
        }
        #pragma unroll
        for (int i = 0; i < 4; i++) {
            int c = tid + (i << 7);
            int k = c >> 5, n4 = (c & 31) << 2;
            __pipeline_memcpy_async(bS + k * BPAD + n4,
                                    Bb + (size_t)(k0 + k) * N + n4, 16);
        }
    };

    uint32_t smb = smem_u32(sm);
    uint32_t aAddr[4];
    #pragma unroll
    for (int mt = 0; mt < 4; mt++)
        aAddr[mt] = smb + ((wm + mt * 16 + (lane & 15)) * APAD) * 4
                        + (lane >> 4) * 16;

    float acc[4][8][4];
    #pragma unroll
    for (int mt = 0; mt < 4; mt++)
        #pragma unroll
        for (int nt = 0; nt < 8; nt++)
            #pragma unroll
            for (int c = 0; c < 4; c++) acc[mt][nt][c] = 0.f;

    int nT = K >> 4;
    #pragma unroll
    for (int s = 0; s < STG - 1; s++) {
        load_stage(s, s << 4);
        __pipeline_commit();
    }

    int stCur = 0;
    for (int t = 0; t < nT; t++) {
        __pipeline_wait_prior(STG - 2);
        __syncthreads();
        int nx = t + STG - 1;
        int stNx = stCur + (STG - 1);
        if (stNx >= STG) stNx -= STG;
        if (nx < nT) load_stage(stNx, nx << 4);
        __pipeline_commit();

        uint32_t aOff = (uint32_t)(stCur * A_STG * 4);
        const float* bS = Bs + stCur * B_STG;

        #pragma unroll
        for (int kk = 0; kk < BKT; kk += 8) {
            uint32_t af[4][4], bf[8][2];
            #pragma unroll
            for (int mt = 0; mt < 4; mt++)
                ldsm_x4(af[mt][0], af[mt][1], af[mt][2], af[mt][3],
                        aAddr[mt] + aOff + kk * 4);
            #pragma unroll
            for (int nt = 0; nt < 8; nt++) {
                const float* bp = bS + (kk + q) * BPAD + wn + nt * 8 + g;
                bf[nt][0] = __float_as_uint(bp[0]);
                bf[nt][1] = __float_as_uint(bp[4 * BPAD]);
            }
            #pragma unroll
            for (int mt = 0; mt < 4; mt++)
                #pragma unroll
                for (int nt = 0; nt < 8; nt++)
                    mma_tf32(acc[mt][nt], af[mt][0], af[mt][1], af[mt][2], af[mt][3],
                             bf[nt][0], bf[nt][1]);
        }
        if (++stCur == STG) stCur = 0;
    }

    // ----- epilogue -----
    #pragma unroll
    for (int mt = 0; mt < 4; mt++) {
        #pragma unroll
        for (int half = 0; half < 2; half++) {
            int row = m0 + wm + mt * 16 + g + half * 8;
            #pragma unroll
            for (int nt = 0; nt < 8; nt++) {
                int col = n0 + wn + nt * 8 + 2 * q;
                float c0 = acc[mt][nt][half * 2 + 0];
                float c1 = acc[mt][nt][half * 2 + 1];
                if (epi == EPI_QKV3) {
                    int t_ = col / DMODEL;            // 0=q 1=k 2=v
                    int within = col - t_ * DMODEL;
                    const float* bptr = (t_ == 0) ? bias : (t_ == 1) ? bias2 : bias3;
                    float2 bv = *(const float2*)&bptr[within];
                    c0 = tf32r(c0 + bv.x); c1 = tf32r(c1 + bv.y);
                    int b_ = row >> 11, s_ = row & 2047;
                    int h_ = within >> 6, d_ = within & 63;
                    size_t o = (size_t)t_ * (MROWS * DMODEL) +
                               (((size_t)(b_ * NHEADS + h_) * SEQ + s_) << 6) + d_;
                    *(float2*)&C[o] = make_float2(c0, c1);
                } else {
                    float2 bv = *(const float2*)&bias[col];
                    c0 += bv.x; c1 += bv.y;
                    if (epi == EPI_RELU) {
                        c0 = tf32r(fmaxf(c0, 0.f));
                        c1 = tf32r(fmaxf(c1, 0.f));
                    } else if (epi == EPI_RES) {
                        float2 r2 = *(const float2*)&res[(size_t)row * N + col];
                        c0 += r2.x; c1 += r2.y;
                    }
                    *(float2*)&C[(size_t)row * N + col] = make_float2(c0, c1);
                }
            }
        }
    }
}

// =====================================================================
// tf32 mma.sync flash attention (R15 WIN: single-buffer, 2 CTAs/SM)
// =====================================================================
#define QS 68
#define KS 68
#define VS 72
#define PS 68
#define NKV 32
#define ATT_SQ   (128*QS)
#define ATT_SK   (64*KS)
#define ATT_SV   (64*VS)
#define ATT_SP   (128*PS)
#define ATTN_SMEM_BYTES ((ATT_SQ + ATT_SK + ATT_SV + ATT_SP)*4 + 64*4)

__global__ void __launch_bounds__(256, 2) attn_mma_kernel(
    const float* __restrict__ Q, const float* __restrict__ K,
    const float* __restrict__ V, const int* __restrict__ mask,
    float* __restrict__ ctx)
{
    extern __shared__ float smf[];
    float* sQ = smf;
    float* sK = sQ + ATT_SQ;
    float* sV = sK + ATT_SK;
    float* sP = sV + ATT_SV;
    int*   sM = (int*)(sP + ATT_SP);

    int tid = threadIdx.x;
    int wid = tid >> 5, lane = tid & 31;
    int g = lane >> 2, q = lane & 3;
    int bh = blockIdx.y;
    int q0 = blockIdx.x * 128;
    int b  = bh / NHEADS;
    int h  = bh % NHEADS;

    const float* Qh = Q + (size_t)bh * SEQ * DK;
    const float* Kh = K + (size_t)bh * SEQ * DK;
    const float* Vh = V + (size_t)bh * SEQ * DK;
    const int* mrow = mask + b * SEQ;

    #pragma unroll
    for (int i = 0; i < 8; i++) {
        int c = tid + 256 * i;
        int r = c >> 4, c4 = (c & 15) << 2;
        *(float4*)&sQ[r * QS + c4] =
            *(const float4*)&Qh[(size_t)(q0 + r) * DK + c4];
    }

    auto loadKV = [&](int kv0) {
        #pragma unroll
        for (int i = 0; i < 4; i++) {
            int c = tid + 256 * i;
            int r = c >> 4, c4 = (c & 15) << 2;
            __pipeline_memcpy_async(&sK[r * KS + c4],
                                    &Kh[(size_t)(kv0 + r) * DK + c4], 16);
            __pipeline_memcpy_async(&sV[r * VS + c4],
                                    &Vh[(size_t)(kv0 + r) * DK + c4], 16);
        }
        if (tid < 64)
            __pipeline_memcpy_async(&sM[tid], &mrow[kv0 + tid], 4);
    };

    float m0 = -1e30f, m1 = -1e30f, l0 = 0.f, l1 = 0.f;
    float oacc[8][4];
    #pragma unroll
    for (int nt = 0; nt < 8; nt++)
        #pragma unroll
        for (int c = 0; c < 4; c++) oacc[nt][c] = 0.f;

    int wr0 = wid * 16;
    __syncthreads();

    for (int t = 0; t < NKV; t++) {
        loadKV(t * 64);
        __pipeline_commit();
        __pipeline_wait_prior(0);
        __syncthreads();

        float sacc[8][4];
        #pragma unroll
        for (int nt = 0; nt < 8; nt++)
            #pragma unroll
            for (int c = 0; c < 4; c++) sacc[nt][c] = 0.f;

        #pragma unroll
        for (int kk = 0; kk < DK; kk += 8) {
            const float* ap = sQ + (wr0 + g) * QS + kk + q;
            uint32_t a0 = __float_as_uint(ap[0]);
            uint32_t a1 = __float_as_uint(ap[8 * QS]);
            uint32_t a2 = __float_as_uint(ap[4]);
            uint32_t a3 = __float_as_uint(ap[8 * QS + 4]);
            #pragma unroll
            for (int nt = 0; nt < 8; nt++) {
                const float* bp = sK + (nt * 8 + g) * KS + kk + q;
                mma_tf32(sacc[nt], a0, a1, a2, a3,
                         __float_as_uint(bp[0]), __float_as_uint(bp[4]));
            }
        }

        float mx0 = -1e30f, mx1 = -1e30f;
        #pragma unroll
        for (int nt = 0; nt < 8; nt++) {
            int c0i = nt * 8 + 2 * q;
            int mva = sM[c0i], mvb = sM[c0i + 1];
            sacc[nt][0] = mva ? sacc[nt][0] * 0.125f : NEGINF;
            sacc[nt][1] = mvb ? sacc[nt][1] * 0.125f : NEGINF;
            sacc[nt][2] = mva ? sacc[nt][2] * 0.125f : NEGINF;
            sacc[nt][3] = mvb ? sacc[nt][3] * 0.125f : NEGINF;
            mx0 = fmaxf(mx0, fmaxf(sacc[nt][0], sacc[nt][1]));
            mx1 = fmaxf(mx1, fmaxf(sacc[nt][2], sacc[nt][3]));
        }
        #pragma unroll
        for (int off = 1; off < 4; off <<= 1) {
            mx0 = fmaxf(mx0, __shfl_xor_sync(0xffffffffu, mx0, off));
            mx1 = fmaxf(mx1, __shfl_xor_sync(0xffffffffu, mx1, off));
        }
        float mn0 = fmaxf(m0, mx0), mn1 = fmaxf(m1, mx1);
        float cor0 = __expf(m0 - mn0), cor1 = __expf(m1 - mn1);
        float ls0 = 0.f, ls1 = 0.f;
        float* pr0 = sP + (wr0 + g) * PS;
        float* pr1 = pr0 + 8 * PS;
        #pragma unroll
        for (int nt = 0; nt < 8; nt++) {
            int c0i = nt * 8 + 2 * q;
            float p0 = __expf(sacc[nt][0] - mn0);
            float p1 = __expf(sacc[nt][1] - mn0);
            float p2 = __expf(sacc[nt][2] - mn1);
            float p3 = __expf(sacc[nt][3] - mn1);
            ls0 += p0 + p1; ls1 += p2 + p3;
            pr0[c0i]     = tf32r(p0);
            pr0[c0i + 1] = tf32r(p1);
            pr1[c0i]     = tf32r(p2);
            pr1[c0i + 1] = tf32r(p3);
        }
        #pragma unroll
        for (int off = 1; off < 4; off <<= 1) {
            ls0 += __shfl_xor_sync(0xffffffffu, ls0, off);
            ls1 += __shfl_xor_sync(0xffffffffu, ls1, off);
        }
        l0 = l0 * cor0 + ls0; m0 = mn0;
        l1 = l1 * cor1 + ls1; m1 = mn1;
        #pragma unroll
        for (int nt = 0; nt < 8; nt++) {
            oacc[nt][0] *= cor0; oacc[nt][1] *= cor0;
            oacc[nt][2] *= cor1; oacc[nt][3] *= cor1;
        }
        __syncwarp();

        #pragma unroll
        for (int kk = 0; kk < 64; kk += 8) {
            const float* ap = sP + (wr0 + g) * PS + kk + q;
            uint32_t a0 = __float_as_uint(ap[0]);
            uint32_t a1 = __float_as_uint(ap[8 * PS]);
            uint32_t a2 = __float_as_uint(ap[4]);
            uint32_t a3 = __float_as_uint(ap[8 * PS + 4]);
            #pragma unroll
            for (int nt = 0; nt < 8; nt++) {
                const float* bp = sV + (kk + q) * VS + nt * 8 + g;
                mma_tf32(oacc[nt], a0, a1, a2, a3,
                         __float_as_uint(bp[0]), __float_as_uint(bp[4 * VS]));
            }
        }
        __syncthreads();
    }

    float inv0 = 1.0f / l0, inv1 = 1.0f / l1;
    size_t row0 = (size_t)(b * SEQ + q0 + wr0 + g);
    size_t row1 = row0 + 8;
    #pragma unroll
    for (int nt = 0; nt < 8; nt++) {
        int col = h * DK + nt * 8 + 2 * q;
        *(float2*)&ctx[row0 * DMODEL + col] =
            make_float2(tf32r(oacc[nt][0] * inv0), tf32r(oacc[nt][1] * inv0));
        *(float2*)&ctx[row1 * DMODEL + col] =
            make_float2(tf32r(oacc[nt][2] * inv1), tf32r(oacc[nt][3] * inv1));
    }
}

// =====================================================================
// launcher
// =====================================================================
extern "C" void kernel_launch(void* const* d_in, const int* in_sizes, int n_in,
                              void* d_out, int out_size)
{
    const float* x    = (const float*)d_in[0];
    const int*   mask = (const int*)  d_in[1];
    const float* wq = (const float*)d_in[2],  *bq = (const float*)d_in[3];
    const float* wk = (const float*)d_in[4],  *bk = (const float*)d_in[5];
    const float* wv = (const float*)d_in[6],  *bv = (const float*)d_in[7];
    const float* wo = (const float*)d_in[8],  *bo = (const float*)d_in[9];
    const float* w1 = (const float*)d_in[10], *b1 = (const float*)d_in[11];
    const float* w2 = (const float*)d_in[12], *b2 = (const float*)d_in[13];
    const float* ln1a = (const float*)d_in[14], *ln1b = (const float*)d_in[15];
    const float* ln2a = (const float*)d_in[16], *ln2b = (const float*)d_in[17];
    float* out = (float*)d_out;

    float *xn, *qkv, *ctx, *x2, *hbuf, *wqkv;
    cudaGetSymbolAddress((void**)&xn,   g_xn);
    cudaGetSymbolAddress((void**)&qkv,  g_qkv);
    cudaGetSymbolAddress((void**)&ctx,  g_ctx);
    cudaGetSymbolAddress((void**)&x2,   g_x2);
    cudaGetSymbolAddress((void**)&hbuf, g_h);
    cudaGetSymbolAddress((void**)&wqkv, g_wqkv);

    cudaFuncSetAttribute(attn_mma_kernel,
                         cudaFuncAttributeMaxDynamicSharedMemorySize,
                         ATTN_SMEM_BYTES);
    cudaFuncSetAttribute(mma_gemm_kernel,
                         cudaFuncAttributeMaxDynamicSharedMemorySize,
                         GEMM_SMEM);

    int n1 = DMODEL * DMODEL / 4;
    trunc_qkv_kernel<<<(n1 + 255) / 256, 256>>>(wq, wk, wv, wqkv);
    // wo/w1/w2 fed raw: tf32 mma truncates operands in HW (RZ vs RNA).

    dim3 gQKV(3 * DMODEL / BN, MROWS / BM);   // (18, 64)
    dim3 g768 (DMODEL / BN, MROWS / BM);      // (6, 64)
    dim3 g3072(DFF    / BN, MROWS / BM);      // (24, 64)

    float* qp = qkv;
    float* kp = qkv + (size_t)MROWS * DMODEL;
    float* vp = qkv + 2 * (size_t)MROWS * DMODEL;

    // sublayer 1
    ln_kernel<<<MROWS / 8, 256>>>(x, xn, ln1a, ln1b);
    mma_gemm_kernel<<<gQKV, 128, GEMM_SMEM>>>(xn, wqkv, bq, bk, bv, nullptr,
                                              qkv, MROWS, 3 * DMODEL, DMODEL, EPI_QKV3);
    attn_mma_kernel<<<dim3(SEQ / 128, BATCH * NHEADS), 256, ATTN_SMEM_BYTES>>>(qp, kp, vp, mask, ctx);
    mma_gemm_kernel<<<g768, 128, GEMM_SMEM>>>(ctx, wo, bo, nullptr, nullptr, x,
                                              x2, MROWS, DMODEL, DMODEL, EPI_RES);

    // sublayer 2
    ln_kernel<<<MROWS / 8, 256>>>(x2, xn, ln2a, ln2b);
    mma_gemm_kernel<<<g3072, 128, GEMM_SMEM>>>(xn, w1, b1, nullptr, nullptr, nullptr,
                                               hbuf, MROWS, DFF, DMODEL, EPI_RELU);
    mma_gemm_kernel<<<g768, 128, GEMM_SMEM>>>(hbuf, w2, b2, nullptr, nullptr, x2,
                                              out, MROWS, DMODEL, DFF, EPI_RES);
}

// round 17
// speedup vs baseline: 1.1678x; 1.0628x over previous
#include <cuda_runtime.h>
#include <cuda_pipeline.h>
#include <math.h>
#include <cstdint>

// ---------------- problem constants ----------------
#define BATCH   4
#define SEQ     2048
#define DMODEL  768
#define NHEADS  12
#define DK      64
#define DFF     3072
#define MROWS   (BATCH*SEQ)          // 8192
#define EPS_LN  1e-6f
#define NEGINF  -1.0e9f

// ---------------- scratch (device globals; allocation-free) ----------------
__device__ float g_xn  [MROWS*DMODEL];
__device__ float g_qkv [3*MROWS*DMODEL];     // [q|k|v], each [B*H, S, 64]
__device__ float g_ctx [MROWS*DMODEL];
__device__ float g_x2  [MROWS*DMODEL];
__device__ float g_h   [MROWS*DFF];
// tf32-rounded concat QKV weights (layout [768][2304] = [wq|wk|wv])
__device__ float g_wqkv[DMODEL*3*DMODEL];

// ---------------- helpers ----------------
__device__ __forceinline__ float tf32r(float x) {
    uint32_t y;
    asm("cvt.rna.tf32.f32 %0, %1;" : "=r"(y) : "f"(x));
    return __uint_as_float(y);
}

__device__ __forceinline__ uint32_t smem_u32(const void* p) {
    uint32_t a;
    asm("{ .reg .u64 t; cvta.to.shared.u64 t, %1; cvt.u32.u64 %0, t; }"
        : "=r"(a) : "l"(p));
    return a;
}

__device__ __forceinline__ void mma_tf32(float* d,
    uint32_t a0, uint32_t a1, uint32_t a2, uint32_t a3,
    uint32_t b0, uint32_t b1)
{
    asm volatile(
        "mma.sync.aligned.m16n8k8.row.col.f32.tf32.tf32.f32 "
        "{%0,%1,%2,%3}, {%4,%5,%6,%7}, {%8,%9}, {%0,%1,%2,%3};"
        : "+f"(d[0]), "+f"(d[1]), "+f"(d[2]), "+f"(d[3])
        : "r"(a0), "r"(a1), "r"(a2), "r"(a3), "r"(b0), "r"(b1));
}

__device__ __forceinline__ void ldsm_x4(uint32_t& r0, uint32_t& r1,
                                        uint32_t& r2, uint32_t& r3, uint32_t a)
{
    asm volatile("ldmatrix.sync.aligned.m8n8.x4.shared.b16 {%0,%1,%2,%3}, [%4];"
                 : "=r"(r0), "=r"(r1), "=r"(r2), "=r"(r3) : "r"(a));
}

// =====================================================================
// QKV concat + tf32-round
// =====================================================================
__global__ void __launch_bounds__(256) trunc_qkv_kernel(
    const float* __restrict__ wq, const float* __restrict__ wk,
    const float* __restrict__ wv, float* __restrict__ out)
{
    int i = blockIdx.x * 256 + threadIdx.x;
    if (i >= DMODEL * DMODEL / 4) return;
    int k = i / (DMODEL / 4);
    int c = (i % (DMODEL / 4)) * 4;
    const float* srcs[3] = {wq, wk, wv};
    #pragma unroll
    for (int t = 0; t < 3; t++) {
        float4 v = *(const float4*)&srcs[t][(size_t)k * DMODEL + c];
        v.x = tf32r(v.x); v.y = tf32r(v.y);
        v.z = tf32r(v.z); v.w = tf32r(v.w);
        *(float4*)&out[(size_t)k * (3 * DMODEL) + t * DMODEL + c] = v;
    }
}

// =====================================================================
// LayerNorm: warp-per-row, 8 rows/block (R8 WIN, unchanged)
// =====================================================================
__global__ void __launch_bounds__(256) ln_kernel(
    const float* __restrict__ x, float* __restrict__ o,
    const float* __restrict__ ga, const float* __restrict__ gb)
{
    int wid = threadIdx.x >> 5, lane = threadIdx.x & 31;
    size_t row = (size_t)blockIdx.x * 8 + wid;
    const float4* xr = (const float4*)(x + row * DMODEL);
    float4 v[6];
    float s = 0.f;
    #pragma unroll
    for (int j = 0; j < 6; j++) {
        v[j] = xr[lane + 32 * j];
        s += v[j].x + v[j].y + v[j].z + v[j].w;
    }
    #pragma unroll
    for (int off = 16; off; off >>= 1) s += __shfl_xor_sync(0xffffffffu, s, off);
    float mean = s * (1.0f / 768.0f);
    float ss = 0.f;
    #pragma unroll
    for (int j = 0; j < 6; j++) {
        v[j].x -= mean; v[j].y -= mean; v[j].z -= mean; v[j].w -= mean;
        ss += v[j].x * v[j].x + v[j].y * v[j].y + v[j].z * v[j].z + v[j].w * v[j].w;
    }
    #pragma unroll
    for (int off = 16; off; off >>= 1) ss += __shfl_xor_sync(0xffffffffu, ss, off);
    float stdv = sqrtf(ss * (1.0f / 767.0f));
    float sc = ga[0] / (EPS_LN + stdv);
    float bb = gb[0];
    float4* orow = (float4*)(o + row * DMODEL);
    #pragma unroll
    for (int j = 0; j < 6; j++) {
        float4 w;
        w.x = tf32r(v[j].x * sc + bb);
        w.y = tf32r(v[j].y * sc + bb);
        w.z = tf32r(v[j].z * sc + bb);
        w.w = tf32r(v[j].w * sc + bb);
        orow[lane + 32 * j] = w;
    }
}

// =====================================================================
// tf32 mma.sync GEMM (R14 WIN: 3-stage, 3 CTAs/SM — unchanged)
// =====================================================================
#define EPI_BIAS 0
#define EPI_RELU 1
#define EPI_RES  2
#define EPI_QKV3 3

#define BM 128
#define BN 128
#define BKT 16
#define STG 3
#define APAD 20
#define BPAD 136
#define A_STG (BM*APAD)
#define B_STG (BKT*BPAD)
#define GEMM_SMEM ((STG*(A_STG+B_STG))*4)      // 56832 B

__global__ void __launch_bounds__(128, 3) mma_gemm_kernel(
    const float* __restrict__ A, const float* __restrict__ B,
    const float* __restrict__ bias, const float* __restrict__ bias2,
    const float* __restrict__ bias3, const float* __restrict__ res,
    float* __restrict__ C, int M, int N, int K, int epi)
{
    extern __shared__ float sm[];
    float* As = sm;
    float* Bs = sm + STG * A_STG;

    int tid = threadIdx.x;
    int wid = tid >> 5, lane = tid & 31;
    int g = lane >> 2, q = lane & 3;
    int wm = (wid >> 1) * 64;
    int wn = (wid & 1) * 64;
    int m0 = blockIdx.y * BM, n0 = blockIdx.x * BN;

    const float* Ab = A + (size_t)m0 * K;
    const float* Bb = B + n0;

    auto load_stage = [&](int st, int k0) {
        float* aS = As + st * A_STG;
        float* bS = Bs + st * B_STG;
        #pragma unroll
        for (int i = 0; i < 4; i++) {
            int c = tid + (i << 7);
            int m = c >> 2, k4 = (c & 3) << 2;
            __pipeline_memcpy_async(aS + m * APAD + k4,
                                    Ab + (size_t)m * K + k0 + k4, 16);
        }
        #pragma unroll
        for (int i = 0; i < 4; i++) {
            int c = tid + (i << 7);
            int k = c >> 5, n4 = (c & 31) << 2;
            __pipeline_memcpy_async(bS + k * BPAD + n4,
                                    Bb + (size_t)(k0 + k) * N + n4, 16);
        }
    };

    uint32_t smb = smem_u32(sm);
    uint32_t aAddr[4];
    #pragma unroll
    for (int mt = 0; mt < 4; mt++)
        aAddr[mt] = smb + ((wm + mt * 16 + (lane & 15)) * APAD) * 4
                        + (lane >> 4) * 16;

    float acc[4][8][4];
    #pragma unroll
    for (int mt = 0; mt < 4; mt++)
        #pragma unroll
        for (int nt = 0; nt < 8; nt++)
            #pragma unroll
            for (int c = 0; c < 4; c++) acc[mt][nt][c] = 0.f;

    int nT = K >> 4;
    #pragma unroll
    for (int s = 0; s < STG - 1; s++) {
        load_stage(s, s << 4);
        __pipeline_commit();
    }

    int stCur = 0;
    for (int t = 0; t < nT; t++) {
        __pipeline_wait_prior(STG - 2);
        __syncthreads();
        int nx = t + STG - 1;
        int stNx = stCur + (STG - 1);
        if (stNx >= STG) stNx -= STG;
        if (nx < nT) load_stage(stNx, nx << 4);
        __pipeline_commit();

        uint32_t aOff = (uint32_t)(stCur * A_STG * 4);
        const float* bS = Bs + stCur * B_STG;

        #pragma unroll
        for (int kk = 0; kk < BKT; kk += 8) {
            uint32_t af[4][4], bf[8][2];
            #pragma unroll
            for (int mt = 0; mt < 4; mt++)
                ldsm_x4(af[mt][0], af[mt][1], af[mt][2], af[mt][3],
                        aAddr[mt] + aOff + kk * 4);
            #pragma unroll
            for (int nt = 0; nt < 8; nt++) {
                const float* bp = bS + (kk + q) * BPAD + wn + nt * 8 + g;
                bf[nt][0] = __float_as_uint(bp[0]);
                bf[nt][1] = __float_as_uint(bp[4 * BPAD]);
            }
            #pragma unroll
            for (int mt = 0; mt < 4; mt++)
                #pragma unroll
                for (int nt = 0; nt < 8; nt++)
                    mma_tf32(acc[mt][nt], af[mt][0], af[mt][1], af[mt][2], af[mt][3],
                             bf[nt][0], bf[nt][1]);
        }
        if (++stCur == STG) stCur = 0;
    }

    // ----- epilogue -----
    #pragma unroll
    for (int mt = 0; mt < 4; mt++) {
        #pragma unroll
        for (int half = 0; half < 2; half++) {
            int row = m0 + wm + mt * 16 + g + half * 8;
            #pragma unroll
            for (int nt = 0; nt < 8; nt++) {
                int col = n0 + wn + nt * 8 + 2 * q;
                float c0 = acc[mt][nt][half * 2 + 0];
                float c1 = acc[mt][nt][half * 2 + 1];
                if (epi == EPI_QKV3) {
                    int t_ = col / DMODEL;            // 0=q 1=k 2=v
                    int within = col - t_ * DMODEL;
                    const float* bptr = (t_ == 0) ? bias : (t_ == 1) ? bias2 : bias3;
                    float2 bv = *(const float2*)&bptr[within];
                    c0 = tf32r(c0 + bv.x); c1 = tf32r(c1 + bv.y);
                    int b_ = row >> 11, s_ = row & 2047;
                    int h_ = within >> 6, d_ = within & 63;
                    size_t o = (size_t)t_ * (MROWS * DMODEL) +
                               (((size_t)(b_ * NHEADS + h_) * SEQ + s_) << 6) + d_;
                    *(float2*)&C[o] = make_float2(c0, c1);
                } else {
                    float2 bv = *(const float2*)&bias[col];
                    c0 += bv.x; c1 += bv.y;
                    if (epi == EPI_RELU) {
                        c0 = tf32r(fmaxf(c0, 0.f));
                        c1 = tf32r(fmaxf(c1, 0.f));
                    } else if (epi == EPI_RES) {
                        float2 r2 = *(const float2*)&res[(size_t)row * N + col];
                        c0 += r2.x; c1 += r2.y;
                    }
                    *(float2*)&C[(size_t)row * N + col] = make_float2(c0, c1);
                }
            }
        }
    }
}

// =====================================================================
// tf32 mma.sync flash attention v2: 128 threads, 4 warps x 32 q-rows
// (2 m-tiles per warp) — B fragments (K/V) reused across 2 MMAs,
// halving B-side LDS traffic in the L1-bound mainloop.
// Single-buffered K/V, 2 CTAs/SM (smem 105.9 KB unchanged).
// =====================================================================
#define QS 68
#define KS 68
#define VS 72
#define PS 68
#define NKV 32
#define ATT_SQ   (128*QS)
#define ATT_SK   (64*KS)
#define ATT_SV   (64*VS)
#define ATT_SP   (128*PS)
#define ATTN_SMEM_BYTES ((ATT_SQ + ATT_SK + ATT_SV + ATT_SP)*4 + 64*4)

__global__ void __launch_bounds__(128, 2) attn_mma_kernel(
    const float* __restrict__ Q, const float* __restrict__ K,
    const float* __restrict__ V, const int* __restrict__ mask,
    float* __restrict__ ctx)
{
    extern __shared__ float smf[];
    float* sQ = smf;                     // [128][QS]
    float* sK = sQ + ATT_SQ;             // [64][KS]
    float* sV = sK + ATT_SK;             // [64][VS]
    float* sP = sV + ATT_SV;             // [128][PS]
    int*   sM = (int*)(sP + ATT_SP);     // [64]

    int tid = threadIdx.x;
    int wid = tid >> 5, lane = tid & 31;
    int g = lane >> 2, q = lane & 3;
    int bh = blockIdx.y;
    int q0 = blockIdx.x * 128;
    int b  = bh / NHEADS;
    int h  = bh % NHEADS;

    const float* Qh = Q + (size_t)bh * SEQ * DK;
    const float* Kh = K + (size_t)bh * SEQ * DK;
    const float* Vh = V + (size_t)bh * SEQ * DK;
    const int* mrow = mask + b * SEQ;

    // Q tile: 2048 float4 / 128 thr = 16 each
    #pragma unroll
    for (int i = 0; i < 16; i++) {
        int c = tid + 128 * i;
        int r = c >> 4, c4 = (c & 15) << 2;
        *(float4*)&sQ[r * QS + c4] =
            *(const float4*)&Qh[(size_t)(q0 + r) * DK + c4];
    }

    auto loadKV = [&](int kv0) {
        #pragma unroll
        for (int i = 0; i < 8; i++) {
            int c = tid + 128 * i;
            int r = c >> 4, c4 = (c & 15) << 2;
            __pipeline_memcpy_async(&sK[r * KS + c4],
                                    &Kh[(size_t)(kv0 + r) * DK + c4], 16);
            __pipeline_memcpy_async(&sV[r * VS + c4],
                                    &Vh[(size_t)(kv0 + r) * DK + c4], 16);
        }
        if (tid < 64)
            __pipeline_memcpy_async(&sM[tid], &mrow[kv0 + tid], 4);
    };

    float m_[2][2], l_[2][2];
    float oacc[2][8][4];
    #pragma unroll
    for (int mt = 0; mt < 2; mt++) {
        m_[mt][0] = -1e30f; m_[mt][1] = -1e30f;
        l_[mt][0] = 0.f;    l_[mt][1] = 0.f;
        #pragma unroll
        for (int nt = 0; nt < 8; nt++)
            #pragma unroll
            for (int c = 0; c < 4; c++) oacc[mt][nt][c] = 0.f;
    }

    int wr0 = wid * 32;              // warp owns rows [wr0, wr0+32)
    __syncthreads();                 // sQ visible

    for (int t = 0; t < NKV; t++) {
        loadKV(t * 64);
        __pipeline_commit();
        __pipeline_wait_prior(0);
        __syncthreads();

        // ---- S = Q @ K^T (2 m-tiles share each B fragment) ----
        float sacc[2][8][4];
        #pragma unroll
        for (int mt = 0; mt < 2; mt++)
            #pragma unroll
            for (int nt = 0; nt < 8; nt++)
                #pragma unroll
                for (int c = 0; c < 4; c++) sacc[mt][nt][c] = 0.f;

        #pragma unroll
        for (int kk = 0; kk < DK; kk += 8) {
            uint32_t a[2][4];
            #pragma unroll
            for (int mt = 0; mt < 2; mt++) {
                const float* ap = sQ + (wr0 + mt * 16 + g) * QS + kk + q;
                a[mt][0] = __float_as_uint(ap[0]);
                a[mt][1] = __float_as_uint(ap[8 * QS]);
                a[mt][2] = __float_as_uint(ap[4]);
                a[mt][3] = __float_as_uint(ap[8 * QS + 4]);
            }
            #pragma unroll
            for (int nt = 0; nt < 8; nt++) {
                const float* bp = sK + (nt * 8 + g) * KS + kk + q;
                uint32_t b0 = __float_as_uint(bp[0]);
                uint32_t b1 = __float_as_uint(bp[4]);
                #pragma unroll
                for (int mt = 0; mt < 2; mt++)
                    mma_tf32(sacc[mt][nt], a[mt][0], a[mt][1], a[mt][2], a[mt][3],
                             b0, b1);
            }
        }

        // ---- scale + mask + online softmax (per m-tile) ----
        #pragma unroll
        for (int mt = 0; mt < 2; mt++) {
            float mx0 = -1e30f, mx1 = -1e30f;
            #pragma unroll
            for (int nt = 0; nt < 8; nt++) {
                int c0i = nt * 8 + 2 * q;
                int mva = sM[c0i], mvb = sM[c0i + 1];
                sacc[mt][nt][0] = mva ? sacc[mt][nt][0] * 0.125f : NEGINF;
                sacc[mt][nt][1] = mvb ? sacc[mt][nt][1] * 0.125f : NEGINF;
                sacc[mt][nt][2] = mva ? sacc[mt][nt][2] * 0.125f : NEGINF;
                sacc[mt][nt][3] = mvb ? sacc[mt][nt][3] * 0.125f : NEGINF;
                mx0 = fmaxf(mx0, fmaxf(sacc[mt][nt][0], sacc[mt][nt][1]));
                mx1 = fmaxf(mx1, fmaxf(sacc[mt][nt][2], sacc[mt][nt][3]));
            }
            #pragma unroll
            for (int off = 1; off < 4; off <<= 1) {
                mx0 = fmaxf(mx0, __shfl_xor_sync(0xffffffffu, mx0, off));
                mx1 = fmaxf(mx1, __shfl_xor_sync(0xffffffffu, mx1, off));
            }
            float mn0 = fmaxf(m_[mt][0], mx0), mn1 = fmaxf(m_[mt][1], mx1);
            float cor0 = __expf(m_[mt][0] - mn0), cor1 = __expf(m_[mt][1] - mn1);
            float ls0 = 0.f, ls1 = 0.f;
            float* pr0 = sP + (wr0 + mt * 16 + g) * PS;
            float* pr1 = pr0 + 8 * PS;
            #pragma unroll
            for (int nt = 0; nt < 8; nt++) {
                int c0i = nt * 8 + 2 * q;
                float p0 = __expf(sacc[mt][nt][0] - mn0);
                float p1 = __expf(sacc[mt][nt][1] - mn0);
                float p2 = __expf(sacc[mt][nt][2] - mn1);
                float p3 = __expf(sacc[mt][nt][3] - mn1);
                ls0 += p0 + p1; ls1 += p2 + p3;
                pr0[c0i]     = tf32r(p0);
                pr0[c0i + 1] = tf32r(p1);
                pr1[c0i]     = tf32r(p2);
                pr1[c0i + 1] = tf32r(p3);
            }
            #pragma unroll
            for (int off = 1; off < 4; off <<= 1) {
                ls0 += __shfl_xor_sync(0xffffffffu, ls0, off);
                ls1 += __shfl_xor_sync(0xffffffffu, ls1, off);
            }
            l_[mt][0] = l_[mt][0] * cor0 + ls0; m_[mt][0] = mn0;
            l_[mt][1] = l_[mt][1] * cor1 + ls1; m_[mt][1] = mn1;
            #pragma unroll
            for (int nt = 0; nt < 8; nt++) {
                oacc[mt][nt][0] *= cor0; oacc[mt][nt][1] *= cor0;
                oacc[mt][nt][2] *= cor1; oacc[mt][nt][3] *= cor1;
            }
        }
        __syncwarp();

        // ---- O += P @ V (2 m-tiles share each B fragment) ----
        #pragma unroll
        for (int kk = 0; kk < 64; kk += 8) {
            uint32_t a[2][4];
            #pragma unroll
            for (int mt = 0; mt < 2; mt++) {
                const float* ap = sP + (wr0 + mt * 16 + g) * PS + kk + q;
                a[mt][0] = __float_as_uint(ap[0]);
                a[mt][1] = __float_as_uint(ap[8 * PS]);
                a[mt][2] = __float_as_uint(ap[4]);
                a[mt][3] = __float_as_uint(ap[8 * PS + 4]);
            }
            #pragma unroll
            for (int nt = 0; nt < 8; nt++) {
                const float* bp = sV + (kk + q) * VS + nt * 8 + g;
                uint32_t b0 = __float_as_uint(bp[0]);
                uint32_t b1 = __float_as_uint(bp[4 * VS]);
                #pragma unroll
                for (int mt = 0; mt < 2; mt++)
                    mma_tf32(oacc[mt][nt], a[mt][0], a[mt][1], a[mt][2], a[mt][3],
                             b0, b1);
            }
        }
        __syncthreads();   // all warps done with sK/sV before next overwrite
    }

    // ---- final: divide by l, store ctx [B,S,DMODEL] ----
    #pragma unroll
    for (int mt = 0; mt < 2; mt++) {
        float inv0 = 1.0f / l_[mt][0], inv1 = 1.0f / l_[mt][1];
        size_t row0 = (size_t)(b * SEQ + q0 + wr0 + mt * 16 + g);
        size_t row1 = row0 + 8;
        #pragma unroll
        for (int nt = 0; nt < 8; nt++) {
            int col = h * DK + nt * 8 + 2 * q;
            *(float2*)&ctx[row0 * DMODEL + col] =
                make_float2(tf32r(oacc[mt][nt][0] * inv0), tf32r(oacc[mt][nt][1] * inv0));
            *(float2*)&ctx[row1 * DMODEL + col] =
                make_float2(tf32r(oacc[mt][nt][2] * inv1), tf32r(oacc[mt][nt][3] * inv1));
        }
    }
}

// =====================================================================
// launcher
// =====================================================================
extern "C" void kernel_launch(void* const* d_in, const int* in_sizes, int n_in,
                              void* d_out, int out_size)
{
    const float* x    = (const float*)d_in[0];
    const int*   mask = (const int*)  d_in[1];
    const float* wq = (const float*)d_in[2],  *bq = (const float*)d_in[3];
    const float* wk = (const float*)d_in[4],  *bk = (const float*)d_in[5];
    const float* wv = (const float*)d_in[6],  *bv = (const float*)d_in[7];
    const float* wo = (const float*)d_in[8],  *bo = (const float*)d_in[9];
    const float* w1 = (const float*)d_in[10], *b1 = (const float*)d_in[11];
    const float* w2 = (const float*)d_in[12], *b2 = (const float*)d_in[13];
    const float* ln1a = (const float*)d_in[14], *ln1b = (const float*)d_in[15];
    const float* ln2a = (const float*)d_in[16], *ln2b = (const float*)d_in[17];
    float* out = (float*)d_out;

    float *xn, *qkv, *ctx, *x2, *hbuf, *wqkv;
    cudaGetSymbolAddress((void**)&xn,   g_xn);
    cudaGetSymbolAddress((void**)&qkv,  g_qkv);
    cudaGetSymbolAddress((void**)&ctx,  g_ctx);
    cudaGetSymbolAddress((void**)&x2,   g_x2);
    cudaGetSymbolAddress((void**)&hbuf, g_h);
    cudaGetSymbolAddress((void**)&wqkv, g_wqkv);

    cudaFuncSetAttribute(attn_mma_kernel,
                         cudaFuncAttributeMaxDynamicSharedMemorySize,
                         ATTN_SMEM_BYTES);
    cudaFuncSetAttribute(mma_gemm_kernel,
                         cudaFuncAttributeMaxDynamicSharedMemorySize,
                         GEMM_SMEM);

    int n1 = DMODEL * DMODEL / 4;
    trunc_qkv_kernel<<<(n1 + 255) / 256, 256>>>(wq, wk, wv, wqkv);
    // wo/w1/w2 fed raw: tf32 mma truncates operands in HW.

    dim3 gQKV(3 * DMODEL / BN, MROWS / BM);   // (18, 64)
    dim3 g768 (DMODEL / BN, MROWS / BM);      // (6, 64)
    dim3 g3072(DFF    / BN, MROWS / BM);      // (24, 64)

    float* qp = qkv;
    float* kp = qkv + (size_t)MROWS * DMODEL;
    float* vp = qkv + 2 * (size_t)MROWS * DMODEL;

    // sublayer 1
    ln_kernel<<<MROWS / 8, 256>>>(x, xn, ln1a, ln1b);
    mma_gemm_kernel<<<gQKV, 128, GEMM_SMEM>>>(xn, wqkv, bq, bk, bv, nullptr,
                                              qkv, MROWS, 3 * DMODEL, DMODEL, EPI_QKV3);
    attn_mma_kernel<<<dim3(SEQ / 128, BATCH * NHEADS), 128, ATTN_SMEM_BYTES>>>(qp, kp, vp, mask, ctx);
    mma_gemm_kernel<<<g768, 128, GEMM_SMEM>>>(ctx, wo, bo, nullptr, nullptr, x,
                                              x2, MROWS, DMODEL, DMODEL, EPI_RES);

    // sublayer 2
    ln_kernel<<<MROWS / 8, 256>>>(x2, xn, ln2a, ln2b);
    mma_gemm_kernel<<<g3072, 128, GEMM_SMEM>>>(xn, w1, b1, nullptr, nullptr, nullptr,
                                               hbuf, MROWS, DFF, DMODEL, EPI_RELU);
    mma_gemm_kernel<<<g768, 128, GEMM_SMEM>>>(hbuf, w2, b2, nullptr, nullptr, x2,
                                              out, MROWS, DMODEL, DFF, EPI_RES);
}